// round 3
// baseline (speedup 1.0000x reference)
#include <cuda_runtime.h>

#define MEM   1000
#define KEY   64
#define VAL   128
#define DIN   512
#define BSS   512
#define BQ    65536

// ---------------- device scratch (no allocations allowed) ----------------
__device__ __align__(16) float g_support_feat[BSS * KEY];
__device__ __align__(16) float g_proj_keys[BSS * KEY];
__device__ __align__(16) float g_proj_vals[BSS * VAL];
__device__             int   g_rank[MEM];
__device__ __align__(16) float g_new_keys[MEM * KEY];
__device__ __align__(16) float g_new_values[MEM * VAL];
__device__ __align__(16) float g_query_feat[BQ * KEY];
__device__ __align__(16) float g_proj_q[BQ * KEY];
__device__ __align__(16) float g_retr_fb[BQ * VAL];   // fallback if out too small
__device__ __align__(16) float g_pred_fb[BQ];
__device__             float g_loss_part[BQ / 64];

// ---------------- tiny generic linear: Y[r,c] = X[r,:K] @ W[:K,c] + b[c] ----------------
__global__ void k_linear(const float* __restrict__ X, const float* __restrict__ W,
                         const float* __restrict__ b, float* __restrict__ Y,
                         int K, int N) {
    int idx = blockIdx.x * blockDim.x + threadIdx.x;
    int r = idx / N, c = idx % N;
    float acc = b[c];
    const float* xr = X + r * K;
    for (int k = 0; k < K; k++) acc += xr[k] * W[k * N + c];
    Y[idx] = acc;
}

// ---------------- rank of each memory slot in descending-age order ----------------
__global__ void k_rank(const float* __restrict__ age) {
    __shared__ float a[MEM];
    int t = threadIdx.x;
    if (t < MEM) a[t] = age[t];
    __syncthreads();
    if (t < MEM) {
        float aj = a[t];
        int cnt = 0;
        for (int i = 0; i < MEM; i++) {
            float ai = a[i];
            cnt += (ai > aj) || (ai == aj && i < t);   // stable tie-break like top_k
        }
        g_rank[t] = cnt;
    }
}

// ---------------- build new_keys / new_values (evict top-BS oldest) ----------------
__global__ void k_scatter(const float* __restrict__ mk, const float* __restrict__ mv) {
    int j = blockIdx.x;
    int r = g_rank[j];
    int t = threadIdx.x;  // 192 threads
    if (t < KEY) {
        g_new_keys[j * KEY + t] = (r < BSS) ? g_proj_keys[r * KEY + t] : mk[j * KEY + t];
    } else {
        int c = t - KEY;
        g_new_values[j * VAL + c] = (r < BSS) ? g_proj_vals[r * VAL + c] : mv[j * VAL + c];
    }
}

// ---------------- fused: query_feat = qx@base_W+b ; proj_q = query_feat@kp_W+kp_b ----------------
#define QF_SMEM_FLOATS (DIN * KEY + 64 * 68 + KEY * KEY)
__global__ void k_qfeat(const float* __restrict__ qx, const float* __restrict__ bW,
                        const float* __restrict__ bb, const float* __restrict__ kpW,
                        const float* __restrict__ kpb) {
    extern __shared__ float sm[];
    float* B_s  = sm;                        // [512][64]
    float* A_s  = sm + DIN * KEY;            // [64][68] (padded)
    float* kp_s = A_s + 64 * 68;             // [64][64]
    int tid = threadIdx.x;
    int tx = tid & 15, ty = tid >> 4;
    int row0 = blockIdx.x * 64;

    for (int i = tid; i < DIN * KEY / 4; i += 256)
        ((float4*)B_s)[i] = ((const float4*)bW)[i];
    for (int i = tid; i < KEY * KEY / 4; i += 256)
        ((float4*)kp_s)[i] = ((const float4*)kpW)[i];

    float acc[4][4];
#pragma unroll
    for (int i = 0; i < 4; i++)
#pragma unroll
        for (int j = 0; j < 4; j++) acc[i][j] = 0.f;

    for (int kc = 0; kc < DIN / 64; kc++) {
        __syncthreads();
        for (int i = tid; i < 4096; i += 256) {
            int r = i >> 6, kk = i & 63;
            A_s[r * 68 + kk] = qx[(row0 + r) * DIN + kc * 64 + kk];
        }
        __syncthreads();
#pragma unroll 8
        for (int k = 0; k < 64; k++) {
            float4 b4 = *(const float4*)&B_s[(kc * 64 + k) * KEY + tx * 4];
            float a0 = A_s[(ty * 4 + 0) * 68 + k];
            float a1 = A_s[(ty * 4 + 1) * 68 + k];
            float a2 = A_s[(ty * 4 + 2) * 68 + k];
            float a3 = A_s[(ty * 4 + 3) * 68 + k];
            acc[0][0] += a0 * b4.x; acc[0][1] += a0 * b4.y; acc[0][2] += a0 * b4.z; acc[0][3] += a0 * b4.w;
            acc[1][0] += a1 * b4.x; acc[1][1] += a1 * b4.y; acc[1][2] += a1 * b4.z; acc[1][3] += a1 * b4.w;
            acc[2][0] += a2 * b4.x; acc[2][1] += a2 * b4.y; acc[2][2] += a2 * b4.z; acc[2][3] += a2 * b4.w;
            acc[3][0] += a3 * b4.x; acc[3][1] += a3 * b4.y; acc[3][2] += a3 * b4.z; acc[3][3] += a3 * b4.w;
        }
    }
    __syncthreads();  // done reading A_s; reuse it as feat_s
    float* feat_s = A_s;
    float4 bias = *(const float4*)&bb[tx * 4];
#pragma unroll
    for (int i = 0; i < 4; i++) {
        int r = ty * 4 + i;
        float4 v = make_float4(acc[i][0] + bias.x, acc[i][1] + bias.y,
                               acc[i][2] + bias.z, acc[i][3] + bias.w);
        *(float4*)&feat_s[r * 68 + tx * 4] = v;
        *(float4*)&g_query_feat[(row0 + r) * KEY + tx * 4] = v;
    }
    __syncthreads();
    float acc2[4][4];
#pragma unroll
    for (int i = 0; i < 4; i++)
#pragma unroll
        for (int j = 0; j < 4; j++) acc2[i][j] = 0.f;
#pragma unroll 8
    for (int k = 0; k < KEY; k++) {
        float4 b4 = *(const float4*)&kp_s[k * KEY + tx * 4];
        float a0 = feat_s[(ty * 4 + 0) * 68 + k];
        float a1 = feat_s[(ty * 4 + 1) * 68 + k];
        float a2 = feat_s[(ty * 4 + 2) * 68 + k];
        float a3 = feat_s[(ty * 4 + 3) * 68 + k];
        acc2[0][0] += a0 * b4.x; acc2[0][1] += a0 * b4.y; acc2[0][2] += a0 * b4.z; acc2[0][3] += a0 * b4.w;
        acc2[1][0] += a1 * b4.x; acc2[1][1] += a1 * b4.y; acc2[1][2] += a1 * b4.z; acc2[1][3] += a1 * b4.w;
        acc2[2][0] += a2 * b4.x; acc2[2][1] += a2 * b4.y; acc2[2][2] += a2 * b4.z; acc2[2][3] += a2 * b4.w;
        acc2[3][0] += a3 * b4.x; acc2[3][1] += a3 * b4.y; acc2[3][2] += a3 * b4.z; acc2[3][3] += a3 * b4.w;
    }
    float4 kb = *(const float4*)&kpb[tx * 4];
#pragma unroll
    for (int i = 0; i < 4; i++) {
        int r = ty * 4 + i;
        float4 v = make_float4(acc2[i][0] + kb.x, acc2[i][1] + kb.y,
                               acc2[i][2] + kb.z, acc2[i][3] + kb.w);
        *(float4*)&g_proj_q[(row0 + r) * KEY + tx * 4] = v;
    }
}

// ---------------- fused attention read: retrieved = softmax(q@K^T) @ V ----------------
// block: 64 query rows, 256 threads (4 threads/row). Online running-max softmax
// (flash-style) — overflow-free. Output stores are SCALAR: out+1+BQ is only
// 4-byte aligned (offset 65537 floats), float4 there traps.
#define AT_CHUNK 100
#define AT_SMEM_FLOATS (AT_CHUNK * KEY + AT_CHUNK * VAL)
__global__ void k_attn(float* __restrict__ outR) {
    extern __shared__ float sm[];
    float* ks = sm;                      // [100][64]
    float* vs = sm + AT_CHUNK * KEY;     // [100][128]
    int tid = threadIdx.x;
    int r = tid >> 2, g = tid & 3;
    int row = blockIdx.x * 64 + r;

    float qr[16];
    const float* qp = g_proj_q + row * KEY + g * 16;
#pragma unroll
    for (int i = 0; i < 16; i += 4) {
        float4 t = *(const float4*)(qp + i);
        qr[i] = t.x; qr[i + 1] = t.y; qr[i + 2] = t.z; qr[i + 3] = t.w;
    }
    float acc[32];
#pragma unroll
    for (int c = 0; c < 32; c++) acc[c] = 0.f;
    float l = 0.f;
    float m = -1e30f;

    for (int ch = 0; ch < MEM / AT_CHUNK; ch++) {
        __syncthreads();
        int m0 = ch * AT_CHUNK;
        for (int i = tid; i < AT_CHUNK * KEY / 4; i += 256)
            ((float4*)ks)[i] = ((const float4*)(g_new_keys + m0 * KEY))[i];
        for (int i = tid; i < AT_CHUNK * VAL / 4; i += 256)
            ((float4*)vs)[i] = ((const float4*)(g_new_values + m0 * VAL))[i];
        __syncthreads();
        for (int j = 0; j < AT_CHUNK; j++) {
            const float* kj = ks + j * KEY + g * 16;
            float s = 0.f;
#pragma unroll
            for (int i = 0; i < 16; i += 4) {
                float4 t = *(const float4*)(kj + i);
                s += qr[i] * t.x + qr[i + 1] * t.y + qr[i + 2] * t.z + qr[i + 3] * t.w;
            }
            s += __shfl_xor_sync(0xffffffffu, s, 1);
            s += __shfl_xor_sync(0xffffffffu, s, 2);
            if (s > m) {                       // new running max: rescale (rare)
                float sc = __expf(m - s);
                l *= sc;
#pragma unroll
                for (int c = 0; c < 32; c++) acc[c] *= sc;
                m = s;
            }
            float w = __expf(s - m);
            l += w;
            const float* vj = vs + j * VAL + g * 32;
#pragma unroll
            for (int c = 0; c < 32; c += 4) {
                float4 t = *(const float4*)(vj + c);
                acc[c] += w * t.x; acc[c + 1] += w * t.y;
                acc[c + 2] += w * t.z; acc[c + 3] += w * t.w;
            }
        }
    }
    float inv = 1.0f / l;
    float* outp = outR + (size_t)row * VAL + g * 32;
#pragma unroll
    for (int c = 0; c < 32; c++)            // scalar stores: 4B-aligned output
        outp[c] = acc[c] * inv;
}

// ---------------- fused controller MLP + per-block loss partial ----------------
#define MLP_W1   24576          /* 192*128 */
#define MLP_AUG  (64 * 193)
#define MLP_H1   (64 * 129)
#define MLP_H2   (64 * 65)
#define MLP_SMEM_FLOATS (MLP_W1 + MLP_AUG + MLP_H1 + MLP_H2 + 64)
__global__ void k_mlp(const float* __restrict__ qy, const float* retrIn, float* predOut,
                      const float* __restrict__ W1, const float* __restrict__ b1,
                      const float* __restrict__ W2, const float* __restrict__ b2,
                      const float* __restrict__ W3, const float* __restrict__ b3) {
    extern __shared__ float sm[];
    float* W1_s  = sm;
    float* aug_s = sm + MLP_W1;
    float* h1_s  = aug_s + MLP_AUG;
    float* h2_s  = h1_s + MLP_H1;
    float* red   = h2_s + MLP_H2;
    int tid = threadIdx.x;
    int row0 = blockIdx.x * 64;

    for (int i = tid; i < MLP_W1 / 4; i += 256)
        ((float4*)W1_s)[i] = ((const float4*)W1)[i];
    for (int i = tid; i < 64 * 192; i += 256) {
        int r = i / 192, c = i % 192;
        float v = (c < KEY) ? g_query_feat[(row0 + r) * KEY + c]
                            : retrIn[(size_t)(row0 + r) * VAL + (c - KEY)];
        aug_s[r * 193 + c] = v;
    }
    __syncthreads();

    {   // h1 = relu(aug @ W1 + b1)   [64 x 128]
        int r = tid & 63, g = tid >> 6;
        float acc[32];
#pragma unroll
        for (int c = 0; c < 32; c++) acc[c] = b1[g * 32 + c];
        for (int k = 0; k < 192; k++) {
            float a = aug_s[r * 193 + k];
            const float* wrow = W1_s + k * 128 + g * 32;
#pragma unroll
            for (int c = 0; c < 32; c += 4) {
                float4 t = *(const float4*)(wrow + c);
                acc[c] += a * t.x; acc[c + 1] += a * t.y;
                acc[c + 2] += a * t.z; acc[c + 3] += a * t.w;
            }
        }
#pragma unroll
        for (int c = 0; c < 32; c++) h1_s[r * 129 + g * 32 + c] = fmaxf(acc[c], 0.f);
    }
    __syncthreads();
    float* W2_s = aug_s;
    for (int i = tid; i < 128 * 64 / 4; i += 256)
        ((float4*)W2_s)[i] = ((const float4*)W2)[i];
    __syncthreads();

    {   // h2 = relu(h1 @ W2 + b2)   [64 x 64]
        int r = tid & 63, g = tid >> 6;
        float acc[16];
#pragma unroll
        for (int c = 0; c < 16; c++) acc[c] = b2[g * 16 + c];
        for (int k = 0; k < 128; k++) {
            float a = h1_s[r * 129 + k];
            const float* wrow = W2_s + k * 64 + g * 16;
#pragma unroll
            for (int c = 0; c < 16; c += 4) {
                float4 t = *(const float4*)(wrow + c);
                acc[c] += a * t.x; acc[c + 1] += a * t.y;
                acc[c + 2] += a * t.z; acc[c + 3] += a * t.w;
            }
        }
#pragma unroll
        for (int c = 0; c < 16; c++) h2_s[r * 65 + g * 16 + c] = fmaxf(acc[c], 0.f);
    }
    __syncthreads();
    {   // pred = h2 @ W3 + b3 ; squared error partial
        int r = tid >> 2, g = tid & 3;
        float s = 0.f;
#pragma unroll
        for (int i = 0; i < 16; i++) s += h2_s[r * 65 + g * 16 + i] * W3[g * 16 + i];
        s += __shfl_xor_sync(0xffffffffu, s, 1);
        s += __shfl_xor_sync(0xffffffffu, s, 2);
        if (g == 0) {
            float p = s + b3[0];
            predOut[row0 + r] = p;
            float d = p - qy[row0 + r];
            red[r] = d * d;
        }
    }
    __syncthreads();
    if (tid < 32) {
        float v = red[tid] + red[tid + 32];
        v += __shfl_xor_sync(0xffffffffu, v, 16);
        v += __shfl_xor_sync(0xffffffffu, v, 8);
        v += __shfl_xor_sync(0xffffffffu, v, 4);
        v += __shfl_xor_sync(0xffffffffu, v, 2);
        v += __shfl_xor_sync(0xffffffffu, v, 1);
        if (tid == 0) g_loss_part[blockIdx.x] = v;
    }
}

// ---------------- deterministic loss finalize ----------------
__global__ void k_finalize(float* __restrict__ out) {
    __shared__ float s[1024];
    int t = threadIdx.x;
    s[t] = g_loss_part[t];
    __syncthreads();
    for (int st = 512; st > 0; st >>= 1) {
        if (t < st) s[t] += s[t + st];
        __syncthreads();
    }
    if (t == 0) out[0] = s[0] / (float)BQ;
}

// ---------------- launcher ----------------
extern "C" void kernel_launch(void* const* d_in, const int* in_sizes, int n_in,
                              void* d_out, int out_size) {
    const float* support_x  = (const float*)d_in[0];
    const float* support_y  = (const float*)d_in[1];
    const float* query_x    = (const float*)d_in[2];
    const float* query_y    = (const float*)d_in[3];
    const float* base_W     = (const float*)d_in[4];
    const float* base_b     = (const float*)d_in[5];
    const float* kp_W       = (const float*)d_in[6];
    const float* kp_b       = (const float*)d_in[7];
    const float* vp_W       = (const float*)d_in[8];
    const float* vp_b       = (const float*)d_in[9];
    const float* mem_keys   = (const float*)d_in[10];
    const float* mem_values = (const float*)d_in[11];
    const float* mem_age    = (const float*)d_in[12];
    const float* c1_W       = (const float*)d_in[13];
    const float* c1_b       = (const float*)d_in[14];
    const float* c2_W       = (const float*)d_in[15];
    const float* c2_b       = (const float*)d_in[16];
    const float* c3_W       = (const float*)d_in[17];
    const float* c3_b       = (const float*)d_in[18];
    float* out = (float*)d_out;

    float *p_sf, *p_pk, *p_pv, *p_pred_fb, *p_retr_fb;
    cudaGetSymbolAddress((void**)&p_sf, g_support_feat);
    cudaGetSymbolAddress((void**)&p_pk, g_proj_keys);
    cudaGetSymbolAddress((void**)&p_pv, g_proj_vals);
    cudaGetSymbolAddress((void**)&p_pred_fb, g_pred_fb);
    cudaGetSymbolAddress((void**)&p_retr_fb, g_retr_fb);

    // direct-into-output layout: [meta_loss(1) | query_pred(BQ) | retrieved(BQ*VAL)]
    float* predBuf = (out_size >= 1 + BQ)            ? out + 1      : p_pred_fb;
    float* retrBuf = (out_size >= 1 + BQ + BQ * VAL) ? out + 1 + BQ : p_retr_fb;

    const int qf_smem  = QF_SMEM_FLOATS * 4;
    const int at_smem  = AT_SMEM_FLOATS * 4;
    const int mlp_smem = MLP_SMEM_FLOATS * 4;
    cudaFuncSetAttribute(k_qfeat, cudaFuncAttributeMaxDynamicSharedMemorySize, qf_smem);
    cudaFuncSetAttribute(k_attn,  cudaFuncAttributeMaxDynamicSharedMemorySize, at_smem);
    cudaFuncSetAttribute(k_mlp,   cudaFuncAttributeMaxDynamicSharedMemorySize, mlp_smem);

    // support pipeline (tiny)
    k_linear<<<BSS * KEY / 256, 256>>>(support_x, base_W, base_b, p_sf, DIN, KEY);
    k_linear<<<BSS * KEY / 256, 256>>>(p_sf, kp_W, kp_b, p_pk, KEY, KEY);
    k_linear<<<BSS * VAL / 256, 256>>>(support_y, vp_W, vp_b, p_pv, VAL, VAL);
    k_rank<<<1, 1024>>>(mem_age);
    k_scatter<<<MEM, 192>>>(mem_keys, mem_values);

    // query pipeline (big)
    k_qfeat<<<BQ / 64, 256, qf_smem>>>(query_x, base_W, base_b, kp_W, kp_b);
    k_attn<<<BQ / 64, 256, at_smem>>>(retrBuf);
    k_mlp<<<BQ / 64, 256, mlp_smem>>>(query_y, retrBuf, predBuf,
                                      c1_W, c1_b, c2_W, c2_b, c3_W, c3_b);
    k_finalize<<<1, 1024>>>(out);
}

// round 4
// speedup vs baseline: 4.1540x; 4.1540x over previous
#include <cuda_runtime.h>

#define MEM   1000
#define NSLOT 1024          /* padded slot count (rows 1000..1023 zero) */
#define KEY   64
#define VAL   128
#define DIN   512
#define BSS   512
#define BQ    65536

// ---------------- packed f32x2 helpers (Blackwell sm_103a) ----------------
#define PACK_F32X2(out, lo, hi) \
    asm("mov.b64 %0, {%1, %2};" : "=l"(out) : "r"(lo), "r"(hi))
#define UNPACK_F32X2(lo, hi, in) \
    asm("mov.b64 {%0, %1}, %2;" : "=r"(lo), "=r"(hi) : "l"(in))
#define FMA_F32X2(d, a, b, c) \
    asm("fma.rn.f32x2 %0, %1, %2, %3;" : "=l"(d) : "l"(a), "l"(b), "l"(c))
#define MUL_F32X2(out, a, b) \
    asm("mul.rn.f32x2 %0, %1, %2;" : "=l"(out) : "l"(a), "l"(b))

// ---------------- device scratch (no allocations allowed) ----------------
__device__ __align__(16) float g_support_feat[BSS * KEY];
__device__ __align__(16) float g_proj_keys[BSS * KEY];
__device__ __align__(16) float g_proj_vals[BSS * VAL];
__device__             int   g_rank[MEM];
__device__ __align__(16) float g_new_keys[NSLOT * KEY];
__device__ __align__(16) float g_new_values[NSLOT * VAL];
__device__ __align__(16) float g_query_feat[BQ * KEY];
__device__ __align__(16) float g_proj_q[BQ * KEY];
__device__ __align__(16) float g_retr_fb[BQ * VAL];   // fallback if out too small
__device__ __align__(16) float g_pred_fb[BQ];
__device__             float g_loss_part[BQ / 64];

// ---------------- tiny generic linear: Y[r,c] = X[r,:K] @ W[:K,c] + b[c] ----------------
__global__ void k_linear(const float* __restrict__ X, const float* __restrict__ W,
                         const float* __restrict__ b, float* __restrict__ Y,
                         int K, int N) {
    int idx = blockIdx.x * blockDim.x + threadIdx.x;
    int r = idx / N, c = idx % N;
    float acc = b[c];
    const float* xr = X + r * K;
    for (int k = 0; k < K; k++) acc += xr[k] * W[k * N + c];
    Y[idx] = acc;
}

// ---------------- rank of each memory slot in descending-age order ----------------
__global__ void k_rank(const float* __restrict__ age) {
    __shared__ float a[MEM];
    int t = threadIdx.x;
    if (t < MEM) a[t] = age[t];
    __syncthreads();
    if (t < MEM) {
        float aj = a[t];
        int cnt = 0;
        for (int i = 0; i < MEM; i++) {
            float ai = a[i];
            cnt += (ai > aj) || (ai == aj && i < t);   // stable tie-break like top_k
        }
        g_rank[t] = cnt;
    }
}

// ---------------- build new_keys / new_values (evict top-BS oldest; zero pad tail) ----------------
__global__ void k_scatter(const float* __restrict__ mk, const float* __restrict__ mv) {
    int j = blockIdx.x;        // 0..NSLOT-1
    int t = threadIdx.x;       // 192 threads
    if (j >= MEM) {            // padded rows: zero (finite so GEMM stays NaN-free)
        if (t < KEY) g_new_keys[j * KEY + t] = 0.f;
        else         g_new_values[j * VAL + (t - KEY)] = 0.f;
        return;
    }
    int r = g_rank[j];
    if (t < KEY) {
        g_new_keys[j * KEY + t] = (r < BSS) ? g_proj_keys[r * KEY + t] : mk[j * KEY + t];
    } else {
        int c = t - KEY;
        g_new_values[j * VAL + c] = (r < BSS) ? g_proj_vals[r * VAL + c] : mv[j * VAL + c];
    }
}

// ---------------- fused: query_feat = qx@base_W+b ; proj_q = query_feat@kp_W+kp_b ----------------
#define QF_SMEM_FLOATS (DIN * KEY + 64 * 68 + KEY * KEY)
__global__ void k_qfeat(const float* __restrict__ qx, const float* __restrict__ bW,
                        const float* __restrict__ bb, const float* __restrict__ kpW,
                        const float* __restrict__ kpb) {
    extern __shared__ float sm[];
    float* B_s  = sm;                        // [512][64]
    float* A_s  = sm + DIN * KEY;            // [64][68] (padded)
    float* kp_s = A_s + 64 * 68;             // [64][64]
    int tid = threadIdx.x;
    int tx = tid & 15, ty = tid >> 4;
    int row0 = blockIdx.x * 64;

    for (int i = tid; i < DIN * KEY / 4; i += 256)
        ((float4*)B_s)[i] = ((const float4*)bW)[i];
    for (int i = tid; i < KEY * KEY / 4; i += 256)
        ((float4*)kp_s)[i] = ((const float4*)kpW)[i];

    float acc[4][4];
#pragma unroll
    for (int i = 0; i < 4; i++)
#pragma unroll
        for (int j = 0; j < 4; j++) acc[i][j] = 0.f;

    for (int kc = 0; kc < DIN / 64; kc++) {
        __syncthreads();
        for (int i = tid; i < 4096; i += 256) {
            int r = i >> 6, kk = i & 63;
            A_s[r * 68 + kk] = qx[(row0 + r) * DIN + kc * 64 + kk];
        }
        __syncthreads();
#pragma unroll 8
        for (int k = 0; k < 64; k++) {
            float4 b4 = *(const float4*)&B_s[(kc * 64 + k) * KEY + tx * 4];
            float a0 = A_s[(ty * 4 + 0) * 68 + k];
            float a1 = A_s[(ty * 4 + 1) * 68 + k];
            float a2 = A_s[(ty * 4 + 2) * 68 + k];
            float a3 = A_s[(ty * 4 + 3) * 68 + k];
            acc[0][0] += a0 * b4.x; acc[0][1] += a0 * b4.y; acc[0][2] += a0 * b4.z; acc[0][3] += a0 * b4.w;
            acc[1][0] += a1 * b4.x; acc[1][1] += a1 * b4.y; acc[1][2] += a1 * b4.z; acc[1][3] += a1 * b4.w;
            acc[2][0] += a2 * b4.x; acc[2][1] += a2 * b4.y; acc[2][2] += a2 * b4.z; acc[2][3] += a2 * b4.w;
            acc[3][0] += a3 * b4.x; acc[3][1] += a3 * b4.y; acc[3][2] += a3 * b4.z; acc[3][3] += a3 * b4.w;
        }
    }
    __syncthreads();  // done reading A_s; reuse it as feat_s
    float* feat_s = A_s;
    float4 bias = *(const float4*)&bb[tx * 4];
#pragma unroll
    for (int i = 0; i < 4; i++) {
        int r = ty * 4 + i;
        float4 v = make_float4(acc[i][0] + bias.x, acc[i][1] + bias.y,
                               acc[i][2] + bias.z, acc[i][3] + bias.w);
        *(float4*)&feat_s[r * 68 + tx * 4] = v;
        *(float4*)&g_query_feat[(row0 + r) * KEY + tx * 4] = v;
    }
    __syncthreads();
    float acc2[4][4];
#pragma unroll
    for (int i = 0; i < 4; i++)
#pragma unroll
        for (int j = 0; j < 4; j++) acc2[i][j] = 0.f;
#pragma unroll 8
    for (int k = 0; k < KEY; k++) {
        float4 b4 = *(const float4*)&kp_s[k * KEY + tx * 4];
        float a0 = feat_s[(ty * 4 + 0) * 68 + k];
        float a1 = feat_s[(ty * 4 + 1) * 68 + k];
        float a2 = feat_s[(ty * 4 + 2) * 68 + k];
        float a3 = feat_s[(ty * 4 + 3) * 68 + k];
        acc2[0][0] += a0 * b4.x; acc2[0][1] += a0 * b4.y; acc2[0][2] += a0 * b4.z; acc2[0][3] += a0 * b4.w;
        acc2[1][0] += a1 * b4.x; acc2[1][1] += a1 * b4.y; acc2[1][2] += a1 * b4.z; acc2[1][3] += a1 * b4.w;
        acc2[2][0] += a2 * b4.x; acc2[2][1] += a2 * b4.y; acc2[2][2] += a2 * b4.z; acc2[2][3] += a2 * b4.w;
        acc2[3][0] += a3 * b4.x; acc2[3][1] += a3 * b4.y; acc2[3][2] += a3 * b4.z; acc2[3][3] += a3 * b4.w;
    }
    float4 kb = *(const float4*)&kpb[tx * 4];
#pragma unroll
    for (int i = 0; i < 4; i++) {
        int r = ty * 4 + i;
        float4 v = make_float4(acc2[i][0] + kb.x, acc2[i][1] + kb.y,
                               acc2[i][2] + kb.z, acc2[i][3] + kb.w);
        *(float4*)&g_proj_q[(row0 + r) * KEY + tx * 4] = v;
    }
}

// ---------------- flash attention, GEMM-structured ----------------
// Block = 64 query rows, 256 threads, CHUNK=64 slots, 16 chunks over 1024 padded.
// GEMM1: S^T[j][r] = K_chunk @ Q^T  (reg-tiled 4x4, padded stride 68, conflict-free)
// exp:   per-chunk branchless online-max, w stored to ws[r][j]
// GEMM2: O[r][c] += W @ V via packed fma.rn.f32x2 (2 FMA/instr)
#define AT_CHUNK 64
#define AT_QT 0
#define AT_KS (64 * 68)
#define AT_VS (2 * 64 * 68)
#define AT_WS (2 * 64 * 68 + 64 * 128)
#define AT_SC (3 * 64 * 68 + 64 * 128)
#define AT_LI (AT_SC + 64)
#define AT_SMEM_FLOATS (AT_LI + 64)
__global__ void k_attn(float* __restrict__ outR) {
    extern __shared__ float sm[];
    float* qT = sm + AT_QT;     // [64k][68] : qT[k*68 + r]
    float* ks = sm + AT_KS;     // [64j][68] : ks[j*68 + k]
    float* vs = sm + AT_VS;     // [64j][128]: vs[j*128 + c]
    float* ws = sm + AT_WS;     // [64r][68] : ws[r*68 + j]  (s then w)
    float* sc = sm + AT_SC;     // [64] per-row rescale
    float* li = sm + AT_LI;     // [64] per-row 1/l
    int tid = threadIdx.x;
    int tx = tid & 15, ty = tid >> 4;
    int r_e = tid >> 2, h = tid & 3;       // exp-phase mapping
    int row0 = blockIdx.x * 64;

    // load Q tile transposed (one time)
    for (int idx = tid; idx < 4096; idx += 256) {
        int r = idx >> 6, k = idx & 63;
        qT[k * 68 + r] = g_proj_q[(row0 + r) * KEY + k];
    }

    unsigned long long acc[4][4];          // [row i][col-pair p] packed f32x2
#pragma unroll
    for (int i = 0; i < 4; i++)
#pragma unroll
        for (int p = 0; p < 4; p++) acc[i][p] = 0ULL;
    float m = -1e30f, l = 0.f;

    for (int ch = 0; ch < NSLOT / AT_CHUNK; ch++) {
        int m0 = ch * AT_CHUNK;
        __syncthreads();   // prev GEMM2 done with vs/ws (and qT stores on first iter)
        for (int q = tid; q < 1024; q += 256) {            // ks: 64x64 as float4
            int j = q >> 4, c4 = q & 15;
            *(float4*)&ks[j * 68 + c4 * 4] =
                *(const float4*)&g_new_keys[(m0 + j) * KEY + c4 * 4];
        }
        for (int q = tid; q < 2048; q += 256)              // vs: straight copy
            ((float4*)vs)[q] = ((const float4*)(g_new_values + m0 * VAL))[q];
        __syncthreads();

        // ---- GEMM1: s[j=ty*4+i][r=tx*4+jj] ----
        float s4[4][4];
#pragma unroll
        for (int i = 0; i < 4; i++)
#pragma unroll
            for (int jj = 0; jj < 4; jj++) s4[i][jj] = 0.f;
#pragma unroll 8
        for (int k = 0; k < 64; k++) {
            float4 b4 = *(const float4*)&qT[k * 68 + tx * 4];
            float a0 = ks[(ty * 4 + 0) * 68 + k];
            float a1 = ks[(ty * 4 + 1) * 68 + k];
            float a2 = ks[(ty * 4 + 2) * 68 + k];
            float a3 = ks[(ty * 4 + 3) * 68 + k];
            s4[0][0] += a0 * b4.x; s4[0][1] += a0 * b4.y; s4[0][2] += a0 * b4.z; s4[0][3] += a0 * b4.w;
            s4[1][0] += a1 * b4.x; s4[1][1] += a1 * b4.y; s4[1][2] += a1 * b4.z; s4[1][3] += a1 * b4.w;
            s4[2][0] += a2 * b4.x; s4[2][1] += a2 * b4.y; s4[2][2] += a2 * b4.z; s4[2][3] += a2 * b4.w;
            s4[3][0] += a3 * b4.x; s4[3][1] += a3 * b4.y; s4[3][2] += a3 * b4.z; s4[3][3] += a3 * b4.w;
        }
#pragma unroll
        for (int i = 0; i < 4; i++)
#pragma unroll
            for (int jj = 0; jj < 4; jj++)
                ws[(tx * 4 + jj) * 68 + ty * 4 + i] = s4[i][jj];   // store transposed -> [r][j]
        __syncthreads();

        // ---- exp phase: row r_e, slots h*16..h*16+15 ----
        {
            int base = h * 16;
            float raw[16];
            float mx = -1e30f;
#pragma unroll
            for (int jj = 0; jj < 16; jj++) {
                float s = ws[r_e * 68 + base + jj];
                raw[jj] = s;
                if ((m0 + base + jj) < MEM && s > mx) mx = s;
            }
            mx = fmaxf(mx, __shfl_xor_sync(0xffffffffu, mx, 1));
            mx = fmaxf(mx, __shfl_xor_sync(0xffffffffu, mx, 2));
            float mnew = fmaxf(m, mx);
            float scl = __expf(m - mnew);
            float ls = 0.f;
#pragma unroll
            for (int jj = 0; jj < 16; jj++) {
                float w = ((m0 + base + jj) < MEM) ? __expf(raw[jj] - mnew) : 0.f;
                ws[r_e * 68 + base + jj] = w;
                ls += w;
            }
            ls += __shfl_xor_sync(0xffffffffu, ls, 1);
            ls += __shfl_xor_sync(0xffffffffu, ls, 2);
            l = l * scl + ls;
            m = mnew;
            if (h == 0) sc[r_e] = scl;
        }
        __syncthreads();

        // ---- GEMM2: acc[r=ty*4+i][c in {tx*4..+3, 64+tx*4..+3}] ----
#pragma unroll
        for (int i = 0; i < 4; i++) {
            float s = sc[ty * 4 + i];
            unsigned long long s2;
            PACK_F32X2(s2, __float_as_uint(s), __float_as_uint(s));
#pragma unroll
            for (int p = 0; p < 4; p++) MUL_F32X2(acc[i][p], acc[i][p], s2);
        }
#pragma unroll 4
        for (int j = 0; j < 64; j++) {
            ulonglong2 bA = *(const ulonglong2*)&vs[j * 128 + tx * 4];
            ulonglong2 bB = *(const ulonglong2*)&vs[j * 128 + 64 + tx * 4];
#pragma unroll
            for (int i = 0; i < 4; i++) {
                float a = ws[(ty * 4 + i) * 68 + j];
                unsigned long long a2;
                PACK_F32X2(a2, __float_as_uint(a), __float_as_uint(a));
                FMA_F32X2(acc[i][0], a2, bA.x, acc[i][0]);
                FMA_F32X2(acc[i][1], a2, bA.y, acc[i][1]);
                FMA_F32X2(acc[i][2], a2, bB.x, acc[i][2]);
                FMA_F32X2(acc[i][3], a2, bB.y, acc[i][3]);
            }
        }
    }

    if (h == 0) li[r_e] = 1.0f / l;
    __syncthreads();

    // epilogue: unpack, normalize, scalar stores (out is only 4B-aligned)
#pragma unroll
    for (int i = 0; i < 4; i++) {
        int row = row0 + ty * 4 + i;
        float linv = li[ty * 4 + i];
        float* op = outR + (size_t)row * VAL;
#pragma unroll
        for (int p = 0; p < 4; p++) {
            unsigned int lo, hi;
            UNPACK_F32X2(lo, hi, acc[i][p]);
            int c = (p < 2) ? (tx * 4 + p * 2) : (64 + tx * 4 + (p - 2) * 2);
            op[c]     = __uint_as_float(lo) * linv;
            op[c + 1] = __uint_as_float(hi) * linv;
        }
    }
}

// ---------------- fused controller MLP + per-block loss partial ----------------
#define MLP_W1   24576          /* 192*128 */
#define MLP_AUG  (64 * 193)
#define MLP_H1   (64 * 129)
#define MLP_H2   (64 * 65)
#define MLP_SMEM_FLOATS (MLP_W1 + MLP_AUG + MLP_H1 + MLP_H2 + 64)
__global__ void k_mlp(const float* __restrict__ qy, const float* retrIn, float* predOut,
                      const float* __restrict__ W1, const float* __restrict__ b1,
                      const float* __restrict__ W2, const float* __restrict__ b2,
                      const float* __restrict__ W3, const float* __restrict__ b3) {
    extern __shared__ float sm[];
    float* W1_s  = sm;
    float* aug_s = sm + MLP_W1;
    float* h1_s  = aug_s + MLP_AUG;
    float* h2_s  = h1_s + MLP_H1;
    float* red   = h2_s + MLP_H2;
    int tid = threadIdx.x;
    int row0 = blockIdx.x * 64;

    for (int i = tid; i < MLP_W1 / 4; i += 256)
        ((float4*)W1_s)[i] = ((const float4*)W1)[i];
    for (int i = tid; i < 64 * 192; i += 256) {
        int r = i / 192, c = i % 192;
        float v = (c < KEY) ? g_query_feat[(row0 + r) * KEY + c]
                            : retrIn[(size_t)(row0 + r) * VAL + (c - KEY)];
        aug_s[r * 193 + c] = v;
    }
    __syncthreads();

    {   // h1 = relu(aug @ W1 + b1)   [64 x 128]
        int r = tid & 63, g = tid >> 6;
        float acc[32];
#pragma unroll
        for (int c = 0; c < 32; c++) acc[c] = b1[g * 32 + c];
        for (int k = 0; k < 192; k++) {
            float a = aug_s[r * 193 + k];
            const float* wrow = W1_s + k * 128 + g * 32;
#pragma unroll
            for (int c = 0; c < 32; c += 4) {
                float4 t = *(const float4*)(wrow + c);
                acc[c] += a * t.x; acc[c + 1] += a * t.y;
                acc[c + 2] += a * t.z; acc[c + 3] += a * t.w;
            }
        }
#pragma unroll
        for (int c = 0; c < 32; c++) h1_s[r * 129 + g * 32 + c] = fmaxf(acc[c], 0.f);
    }
    __syncthreads();
    float* W2_s = aug_s;
    for (int i = tid; i < 128 * 64 / 4; i += 256)
        ((float4*)W2_s)[i] = ((const float4*)W2)[i];
    __syncthreads();

    {   // h2 = relu(h1 @ W2 + b2)   [64 x 64]
        int r = tid & 63, g = tid >> 6;
        float acc[16];
#pragma unroll
        for (int c = 0; c < 16; c++) acc[c] = b2[g * 16 + c];
        for (int k = 0; k < 128; k++) {
            float a = h1_s[r * 129 + k];
            const float* wrow = W2_s + k * 64 + g * 16;
#pragma unroll
            for (int c = 0; c < 16; c += 4) {
                float4 t = *(const float4*)(wrow + c);
                acc[c] += a * t.x; acc[c + 1] += a * t.y;
                acc[c + 2] += a * t.z; acc[c + 3] += a * t.w;
            }
        }
#pragma unroll
        for (int c = 0; c < 16; c++) h2_s[r * 65 + g * 16 + c] = fmaxf(acc[c], 0.f);
    }
    __syncthreads();
    {   // pred = h2 @ W3 + b3 ; squared error partial
        int r = tid >> 2, g = tid & 3;
        float s = 0.f;
#pragma unroll
        for (int i = 0; i < 16; i++) s += h2_s[r * 65 + g * 16 + i] * W3[g * 16 + i];
        s += __shfl_xor_sync(0xffffffffu, s, 1);
        s += __shfl_xor_sync(0xffffffffu, s, 2);
        if (g == 0) {
            float p = s + b3[0];
            predOut[row0 + r] = p;
            float d = p - qy[row0 + r];
            red[r] = d * d;
        }
    }
    __syncthreads();
    if (tid < 32) {
        float v = red[tid] + red[tid + 32];
        v += __shfl_xor_sync(0xffffffffu, v, 16);
        v += __shfl_xor_sync(0xffffffffu, v, 8);
        v += __shfl_xor_sync(0xffffffffu, v, 4);
        v += __shfl_xor_sync(0xffffffffu, v, 2);
        v += __shfl_xor_sync(0xffffffffu, v, 1);
        if (tid == 0) g_loss_part[blockIdx.x] = v;
    }
}

// ---------------- deterministic loss finalize ----------------
__global__ void k_finalize(float* __restrict__ out) {
    __shared__ float s[1024];
    int t = threadIdx.x;
    s[t] = g_loss_part[t];
    __syncthreads();
    for (int st = 512; st > 0; st >>= 1) {
        if (t < st) s[t] += s[t + st];
        __syncthreads();
    }
    if (t == 0) out[0] = s[0] / (float)BQ;
}

// ---------------- launcher ----------------
extern "C" void kernel_launch(void* const* d_in, const int* in_sizes, int n_in,
                              void* d_out, int out_size) {
    const float* support_x  = (const float*)d_in[0];
    const float* support_y  = (const float*)d_in[1];
    const float* query_x    = (const float*)d_in[2];
    const float* query_y    = (const float*)d_in[3];
    const float* base_W     = (const float*)d_in[4];
    const float* base_b     = (const float*)d_in[5];
    const float* kp_W       = (const float*)d_in[6];
    const float* kp_b       = (const float*)d_in[7];
    const float* vp_W       = (const float*)d_in[8];
    const float* vp_b       = (const float*)d_in[9];
    const float* mem_keys   = (const float*)d_in[10];
    const float* mem_values = (const float*)d_in[11];
    const float* mem_age    = (const float*)d_in[12];
    const float* c1_W       = (const float*)d_in[13];
    const float* c1_b       = (const float*)d_in[14];
    const float* c2_W       = (const float*)d_in[15];
    const float* c2_b       = (const float*)d_in[16];
    const float* c3_W       = (const float*)d_in[17];
    const float* c3_b       = (const float*)d_in[18];
    float* out = (float*)d_out;

    float *p_sf, *p_pk, *p_pv, *p_pred_fb, *p_retr_fb;
    cudaGetSymbolAddress((void**)&p_sf, g_support_feat);
    cudaGetSymbolAddress((void**)&p_pk, g_proj_keys);
    cudaGetSymbolAddress((void**)&p_pv, g_proj_vals);
    cudaGetSymbolAddress((void**)&p_pred_fb, g_pred_fb);
    cudaGetSymbolAddress((void**)&p_retr_fb, g_retr_fb);

    // direct-into-output layout: [meta_loss(1) | query_pred(BQ) | retrieved(BQ*VAL)]
    float* predBuf = (out_size >= 1 + BQ)            ? out + 1      : p_pred_fb;
    float* retrBuf = (out_size >= 1 + BQ + BQ * VAL) ? out + 1 + BQ : p_retr_fb;

    const int qf_smem  = QF_SMEM_FLOATS * 4;
    const int at_smem  = AT_SMEM_FLOATS * 4;
    const int mlp_smem = MLP_SMEM_FLOATS * 4;
    cudaFuncSetAttribute(k_qfeat, cudaFuncAttributeMaxDynamicSharedMemorySize, qf_smem);
    cudaFuncSetAttribute(k_attn,  cudaFuncAttributeMaxDynamicSharedMemorySize, at_smem);
    cudaFuncSetAttribute(k_mlp,   cudaFuncAttributeMaxDynamicSharedMemorySize, mlp_smem);

    // support pipeline (tiny)
    k_linear<<<BSS * KEY / 256, 256>>>(support_x, base_W, base_b, p_sf, DIN, KEY);
    k_linear<<<BSS * KEY / 256, 256>>>(p_sf, kp_W, kp_b, p_pk, KEY, KEY);
    k_linear<<<BSS * VAL / 256, 256>>>(support_y, vp_W, vp_b, p_pv, VAL, VAL);
    k_rank<<<1, 1024>>>(mem_age);
    k_scatter<<<NSLOT, 192>>>(mem_keys, mem_values);

    // query pipeline (big)
    k_qfeat<<<BQ / 64, 256, qf_smem>>>(query_x, base_W, base_b, kp_W, kp_b);
    k_attn<<<BQ / 64, 256, at_smem>>>(retrBuf);
    k_mlp<<<BQ / 64, 256, mlp_smem>>>(query_y, retrBuf, predBuf,
                                      c1_W, c1_b, c2_W, c2_b, c3_W, c3_b);
    k_finalize<<<1, 1024>>>(out);
}

// round 5
// speedup vs baseline: 4.6369x; 1.1163x over previous
#include <cuda_runtime.h>

#define MEM   1000
#define NSLOT 1024          /* padded slot count (rows 1000..1023 zero) */
#define KEY   64
#define VAL   128
#define DIN   512
#define BSS   512
#define BQ    65536

typedef unsigned long long u64;

// ---------------- packed f32x2 helpers (Blackwell sm_103a) ----------------
#define PACK_F32X2(out, lo, hi) \
    asm("mov.b64 %0, {%1, %2};" : "=l"(out) : "r"(lo), "r"(hi))
#define PACKF_F32X2(out, a, b) \
    asm("mov.b64 %0, {%1, %2};" : "=l"(out) : "f"(a), "f"(b))
#define UNPACKF_F32X2(a, b, in) \
    asm("mov.b64 {%0, %1}, %2;" : "=f"(a), "=f"(b) : "l"(in))
#define UNPACK_F32X2(lo, hi, in) \
    asm("mov.b64 {%0, %1}, %2;" : "=r"(lo), "=r"(hi) : "l"(in))
#define FMA_F32X2(d, a, b, c) \
    asm("fma.rn.f32x2 %0, %1, %2, %3;" : "=l"(d) : "l"(a), "l"(b), "l"(c))
#define MUL_F32X2(out, a, b) \
    asm("mul.rn.f32x2 %0, %1, %2;" : "=l"(out) : "l"(a), "l"(b))

// ---------------- device scratch (no allocations allowed) ----------------
__device__ __align__(16) float g_support_feat[BSS * KEY];
__device__ __align__(16) float g_proj_keys[BSS * KEY];
__device__ __align__(16) float g_proj_vals[BSS * VAL];
__device__             int   g_rank[MEM];
__device__ __align__(16) float g_new_keys[NSLOT * KEY];
__device__ __align__(16) float g_new_values[NSLOT * VAL];
__device__ __align__(16) float g_query_feat[BQ * KEY];
__device__ __align__(16) float g_proj_q[BQ * KEY];
__device__ __align__(16) float g_retr_fb[BQ * VAL];   // fallback if out too small
__device__ __align__(16) float g_pred_fb[BQ];
__device__             float g_loss_part[BQ / 64];

// ---------------- tiny generic linear: Y[r,c] = X[r,:K] @ W[:K,c] + b[c] ----------------
__global__ void k_linear(const float* __restrict__ X, const float* __restrict__ W,
                         const float* __restrict__ b, float* __restrict__ Y,
                         int K, int N) {
    int idx = blockIdx.x * blockDim.x + threadIdx.x;
    int r = idx / N, c = idx % N;
    float acc = b[c];
    const float* xr = X + r * K;
    for (int k = 0; k < K; k++) acc += xr[k] * W[k * N + c];
    Y[idx] = acc;
}

// ---------------- rank of each memory slot (parallel over 8 blocks) ----------------
__global__ void k_rank(const float* __restrict__ age) {
    __shared__ float a[MEM];
    int t = threadIdx.x;           // 128
    for (int i = t; i < MEM; i += 128) a[i] = age[i];
    __syncthreads();
    int j = blockIdx.x * 128 + t;
    if (j < MEM) {
        float aj = a[j];
        int cnt = 0;
        for (int i = 0; i < MEM; i++) {
            float ai = a[i];
            cnt += (ai > aj) || (ai == aj && i < j);   // stable tie-break like top_k
        }
        g_rank[j] = cnt;
    }
}

// ---------------- build new_keys / new_values (evict top-BS oldest; zero pad tail) ----------------
__global__ void k_scatter(const float* __restrict__ mk, const float* __restrict__ mv) {
    int j = blockIdx.x;        // 0..NSLOT-1
    int t = threadIdx.x;       // 192 threads
    if (j >= MEM) {            // padded rows: zero (finite so GEMM stays NaN-free)
        if (t < KEY) g_new_keys[j * KEY + t] = 0.f;
        else         g_new_values[j * VAL + (t - KEY)] = 0.f;
        return;
    }
    int r = g_rank[j];
    if (t < KEY) {
        g_new_keys[j * KEY + t] = (r < BSS) ? g_proj_keys[r * KEY + t] : mk[j * KEY + t];
    } else {
        int c = t - KEY;
        g_new_values[j * VAL + c] = (r < BSS) ? g_proj_vals[r * VAL + c] : mv[j * VAL + c];
    }
}

// ---------------- fused: query_feat = qx@base_W+b ; proj_q = query_feat@kp_W+kp_b ----------------
// base_W streamed in 64-k chunks (smem 49KB -> 3-4 blocks/SM); inner loop f32x2.
#define QF_BC 0
#define QF_AS (64 * 64)
#define QF_KP (64 * 64 + 64 * 68)
#define QF_SMEM_FLOATS (64 * 64 + 64 * 68 + 64 * 64)
__global__ void k_qfeat(const float* __restrict__ qx, const float* __restrict__ bW,
                        const float* __restrict__ bb, const float* __restrict__ kpW,
                        const float* __restrict__ kpb) {
    extern __shared__ float sm[];
    float* Bc   = sm + QF_BC;     // [64k][64c] current chunk of base_W
    float* A_s  = sm + QF_AS;     // [64r][68]
    float* kp_s = sm + QF_KP;     // [64][64]
    int tid = threadIdx.x;
    int tx = tid & 15, ty = tid >> 4;
    int row0 = blockIdx.x * 64;

    for (int i = tid; i < KEY * KEY / 4; i += 256)
        ((float4*)kp_s)[i] = ((const float4*)kpW)[i];

    u64 acc[4][2];                 // [row i][col-pair p]
#pragma unroll
    for (int i = 0; i < 4; i++) { acc[i][0] = 0ULL; acc[i][1] = 0ULL; }

    for (int kc = 0; kc < DIN / 64; kc++) {
        __syncthreads();
        for (int i = tid; i < 1024; i += 256)          // Bc chunk: contiguous
            ((float4*)Bc)[i] = ((const float4*)(bW + kc * 4096))[i];
        for (int i = tid; i < 4096; i += 256) {
            int r = i >> 6, kk = i & 63;
            A_s[r * 68 + kk] = qx[(row0 + r) * DIN + kc * 64 + kk];
        }
        __syncthreads();
#pragma unroll 8
        for (int k = 0; k < 64; k++) {
            ulonglong2 b2 = *(const ulonglong2*)&Bc[k * 64 + tx * 4];
#pragma unroll
            for (int i = 0; i < 4; i++) {
                float a = A_s[(ty * 4 + i) * 68 + k];
                u64 a2; PACKF_F32X2(a2, a, a);
                FMA_F32X2(acc[i][0], a2, b2.x, acc[i][0]);
                FMA_F32X2(acc[i][1], a2, b2.y, acc[i][1]);
            }
        }
    }
    __syncthreads();  // done reading A_s; reuse it as feat_s
    float* feat_s = A_s;
    float4 bias = *(const float4*)&bb[tx * 4];
#pragma unroll
    for (int i = 0; i < 4; i++) {
        int r = ty * 4 + i;
        float v0, v1, v2, v3;
        UNPACKF_F32X2(v0, v1, acc[i][0]);
        UNPACKF_F32X2(v2, v3, acc[i][1]);
        float4 v = make_float4(v0 + bias.x, v1 + bias.y, v2 + bias.z, v3 + bias.w);
        *(float4*)&feat_s[r * 68 + tx * 4] = v;
        *(float4*)&g_query_feat[(row0 + r) * KEY + tx * 4] = v;
    }
    __syncthreads();

    // proj_q = feat @ kp_W + kp_b  (64-k, f32x2)
    u64 acc2[4][2];
#pragma unroll
    for (int i = 0; i < 4; i++) { acc2[i][0] = 0ULL; acc2[i][1] = 0ULL; }
#pragma unroll 8
    for (int k = 0; k < KEY; k++) {
        ulonglong2 b2 = *(const ulonglong2*)&kp_s[k * KEY + tx * 4];
#pragma unroll
        for (int i = 0; i < 4; i++) {
            float a = feat_s[(ty * 4 + i) * 68 + k];
            u64 a2; PACKF_F32X2(a2, a, a);
            FMA_F32X2(acc2[i][0], a2, b2.x, acc2[i][0]);
            FMA_F32X2(acc2[i][1], a2, b2.y, acc2[i][1]);
        }
    }
    float4 kb = *(const float4*)&kpb[tx * 4];
#pragma unroll
    for (int i = 0; i < 4; i++) {
        int r = ty * 4 + i;
        float v0, v1, v2, v3;
        UNPACKF_F32X2(v0, v1, acc2[i][0]);
        UNPACKF_F32X2(v2, v3, acc2[i][1]);
        float4 v = make_float4(v0 + kb.x, v1 + kb.y, v2 + kb.z, v3 + kb.w);
        *(float4*)&g_proj_q[(row0 + r) * KEY + tx * 4] = v;
    }
}

// ---------------- flash attention, GEMM-structured, f32x2 throughout ----------------
#define AT_CHUNK 64
#define AT_QT 0
#define AT_KS (64 * 68)
#define AT_VS (2 * 64 * 68)
#define AT_WS (2 * 64 * 68 + 64 * 128)
#define AT_SC (3 * 64 * 68 + 64 * 128)
#define AT_LI (AT_SC + 64)
#define AT_SMEM_FLOATS (AT_LI + 64)
__global__ void k_attn(float* __restrict__ outR) {
    extern __shared__ float sm[];
    float* qT = sm + AT_QT;     // [64k][68] : qT[k*68 + r]
    float* ks = sm + AT_KS;     // [64j][68] : ks[j*68 + k]
    float* vs = sm + AT_VS;     // [64j][128]: vs[j*128 + c]
    float* ws = sm + AT_WS;     // [64r][68] : ws[r*68 + j]  (s then w)
    float* sc = sm + AT_SC;     // [64] per-row rescale
    float* li = sm + AT_LI;     // [64] per-row 1/l
    int tid = threadIdx.x;
    int tx = tid & 15, ty = tid >> 4;
    int r_e = tid >> 2, h = tid & 3;       // exp-phase mapping
    int row0 = blockIdx.x * 64;

    // load Q tile transposed (one time)
    for (int idx = tid; idx < 4096; idx += 256) {
        int r = idx >> 6, k = idx & 63;
        qT[k * 68 + r] = g_proj_q[(row0 + r) * KEY + k];
    }

    u64 acc[4][4];          // [row i][col-pair p] packed f32x2
#pragma unroll
    for (int i = 0; i < 4; i++)
#pragma unroll
        for (int p = 0; p < 4; p++) acc[i][p] = 0ULL;
    float m = -1e30f, l = 0.f;

    for (int ch = 0; ch < NSLOT / AT_CHUNK; ch++) {
        int m0 = ch * AT_CHUNK;
        __syncthreads();   // prev GEMM2 done with vs/ws (and qT stores on first iter)
        for (int q = tid; q < 1024; q += 256) {            // ks: 64x64 as float4
            int j = q >> 4, c4 = q & 15;
            *(float4*)&ks[j * 68 + c4 * 4] =
                *(const float4*)&g_new_keys[(m0 + j) * KEY + c4 * 4];
        }
        for (int q = tid; q < 2048; q += 256)              // vs: straight copy
            ((float4*)vs)[q] = ((const float4*)(g_new_values + m0 * VAL))[q];
        __syncthreads();

        // ---- GEMM1 (f32x2): s[j=ty*4+i][r-pairs from tx*4] ----
        u64 s4[4][2];
#pragma unroll
        for (int i = 0; i < 4; i++) { s4[i][0] = 0ULL; s4[i][1] = 0ULL; }
#pragma unroll 8
        for (int k = 0; k < 64; k++) {
            ulonglong2 bq = *(const ulonglong2*)&qT[k * 68 + tx * 4];
#pragma unroll
            for (int i = 0; i < 4; i++) {
                float a = ks[(ty * 4 + i) * 68 + k];
                u64 a2; PACKF_F32X2(a2, a, a);
                FMA_F32X2(s4[i][0], a2, bq.x, s4[i][0]);
                FMA_F32X2(s4[i][1], a2, bq.y, s4[i][1]);
            }
        }
#pragma unroll
        for (int i = 0; i < 4; i++) {
            float v0, v1, v2, v3;
            UNPACKF_F32X2(v0, v1, s4[i][0]);
            UNPACKF_F32X2(v2, v3, s4[i][1]);
            ws[(tx * 4 + 0) * 68 + ty * 4 + i] = v0;   // store transposed -> [r][j]
            ws[(tx * 4 + 1) * 68 + ty * 4 + i] = v1;
            ws[(tx * 4 + 2) * 68 + ty * 4 + i] = v2;
            ws[(tx * 4 + 3) * 68 + ty * 4 + i] = v3;
        }
        __syncthreads();

        // ---- exp phase: row r_e, slots h*16..h*16+15 ----
        {
            int base = h * 16;
            float raw[16];
            float mx = -1e30f;
#pragma unroll
            for (int jj = 0; jj < 16; jj++) {
                float s = ws[r_e * 68 + base + jj];
                raw[jj] = s;
                if ((m0 + base + jj) < MEM && s > mx) mx = s;
            }
            mx = fmaxf(mx, __shfl_xor_sync(0xffffffffu, mx, 1));
            mx = fmaxf(mx, __shfl_xor_sync(0xffffffffu, mx, 2));
            float mnew = fmaxf(m, mx);
            float scl = __expf(m - mnew);
            float ls = 0.f;
#pragma unroll
            for (int jj = 0; jj < 16; jj++) {
                float w = ((m0 + base + jj) < MEM) ? __expf(raw[jj] - mnew) : 0.f;
                ws[r_e * 68 + base + jj] = w;
                ls += w;
            }
            ls += __shfl_xor_sync(0xffffffffu, ls, 1);
            ls += __shfl_xor_sync(0xffffffffu, ls, 2);
            l = l * scl + ls;
            m = mnew;
            if (h == 0) sc[r_e] = scl;
        }
        __syncthreads();

        // ---- GEMM2 (f32x2): acc[r=ty*4+i][c in {tx*4..+3, 64+tx*4..+3}] ----
#pragma unroll
        for (int i = 0; i < 4; i++) {
            float s = sc[ty * 4 + i];
            u64 s2; PACKF_F32X2(s2, s, s);
#pragma unroll
            for (int p = 0; p < 4; p++) MUL_F32X2(acc[i][p], acc[i][p], s2);
        }
#pragma unroll 4
        for (int j = 0; j < 64; j++) {
            ulonglong2 bA = *(const ulonglong2*)&vs[j * 128 + tx * 4];
            ulonglong2 bB = *(const ulonglong2*)&vs[j * 128 + 64 + tx * 4];
#pragma unroll
            for (int i = 0; i < 4; i++) {
                float a = ws[(ty * 4 + i) * 68 + j];
                u64 a2; PACKF_F32X2(a2, a, a);
                FMA_F32X2(acc[i][0], a2, bA.x, acc[i][0]);
                FMA_F32X2(acc[i][1], a2, bA.y, acc[i][1]);
                FMA_F32X2(acc[i][2], a2, bB.x, acc[i][2]);
                FMA_F32X2(acc[i][3], a2, bB.y, acc[i][3]);
            }
        }
    }

    if (h == 0) li[r_e] = 1.0f / l;
    __syncthreads();

    // epilogue: unpack, normalize, scalar stores (out is only 4B-aligned)
#pragma unroll
    for (int i = 0; i < 4; i++) {
        int row = row0 + ty * 4 + i;
        float linv = li[ty * 4 + i];
        float* op = outR + (size_t)row * VAL;
#pragma unroll
        for (int p = 0; p < 4; p++) {
            float lo, hi;
            UNPACKF_F32X2(lo, hi, acc[i][p]);
            int c = (p < 2) ? (tx * 4 + p * 2) : (64 + tx * 4 + (p - 2) * 2);
            op[c]     = lo * linv;
            op[c + 1] = hi * linv;
        }
    }
}

// ---------------- fused controller MLP + per-block loss partial (f32x2) ----------------
#define MLP_W1   24576          /* 192*128 */
#define MLP_AUG  (64 * 193)
#define MLP_H1   (64 * 129)
#define MLP_H2   (64 * 65)
#define MLP_SMEM_FLOATS (MLP_W1 + MLP_AUG + MLP_H1 + MLP_H2 + 64)
__global__ void k_mlp(const float* __restrict__ qy, const float* retrIn, float* predOut,
                      const float* __restrict__ W1, const float* __restrict__ b1,
                      const float* __restrict__ W2, const float* __restrict__ b2,
                      const float* __restrict__ W3, const float* __restrict__ b3) {
    extern __shared__ float sm[];
    float* W1_s  = sm;
    float* aug_s = sm + MLP_W1;
    float* h1_s  = aug_s + MLP_AUG;
    float* h2_s  = h1_s + MLP_H1;
    float* red   = h2_s + MLP_H2;
    int tid = threadIdx.x;
    int row0 = blockIdx.x * 64;

    for (int i = tid; i < MLP_W1 / 4; i += 256)
        ((float4*)W1_s)[i] = ((const float4*)W1)[i];
    for (int i = tid; i < 64 * 192; i += 256) {
        int r = i / 192, c = i % 192;
        float v = (c < KEY) ? g_query_feat[(row0 + r) * KEY + c]
                            : retrIn[(size_t)(row0 + r) * VAL + (c - KEY)];
        aug_s[r * 193 + c] = v;
    }
    __syncthreads();

    {   // h1 = relu(aug @ W1 + b1)   [64 x 128], f32x2: 16 col-pairs/thread
        int r = tid & 63, g = tid >> 6;
        u64 acc[16];
#pragma unroll
        for (int c = 0; c < 16; c++) {
            float x = b1[g * 32 + 2 * c], y = b1[g * 32 + 2 * c + 1];
            PACKF_F32X2(acc[c], x, y);
        }
        for (int k = 0; k < 192; k++) {
            float a = aug_s[r * 193 + k];
            u64 a2; PACKF_F32X2(a2, a, a);
            const ulonglong2* wr = (const ulonglong2*)(W1_s + k * 128 + g * 32);
#pragma unroll
            for (int q = 0; q < 8; q++) {
                ulonglong2 w = wr[q];
                FMA_F32X2(acc[2 * q],     a2, w.x, acc[2 * q]);
                FMA_F32X2(acc[2 * q + 1], a2, w.y, acc[2 * q + 1]);
            }
        }
#pragma unroll
        for (int c = 0; c < 16; c++) {
            float x, y;
            UNPACKF_F32X2(x, y, acc[c]);
            h1_s[r * 129 + g * 32 + 2 * c]     = fmaxf(x, 0.f);
            h1_s[r * 129 + g * 32 + 2 * c + 1] = fmaxf(y, 0.f);
        }
    }
    __syncthreads();
    float* W2_s = aug_s;
    for (int i = tid; i < 128 * 64 / 4; i += 256)
        ((float4*)W2_s)[i] = ((const float4*)W2)[i];
    __syncthreads();

    {   // h2 = relu(h1 @ W2 + b2)   [64 x 64], f32x2: 8 col-pairs/thread
        int r = tid & 63, g = tid >> 6;
        u64 acc[8];
#pragma unroll
        for (int c = 0; c < 8; c++) {
            float x = b2[g * 16 + 2 * c], y = b2[g * 16 + 2 * c + 1];
            PACKF_F32X2(acc[c], x, y);
        }
        for (int k = 0; k < 128; k++) {
            float a = h1_s[r * 129 + k];
            u64 a2; PACKF_F32X2(a2, a, a);
            const ulonglong2* wr = (const ulonglong2*)(W2_s + k * 64 + g * 16);
#pragma unroll
            for (int q = 0; q < 4; q++) {
                ulonglong2 w = wr[q];
                FMA_F32X2(acc[2 * q],     a2, w.x, acc[2 * q]);
                FMA_F32X2(acc[2 * q + 1], a2, w.y, acc[2 * q + 1]);
            }
        }
#pragma unroll
        for (int c = 0; c < 8; c++) {
            float x, y;
            UNPACKF_F32X2(x, y, acc[c]);
            h2_s[r * 65 + g * 16 + 2 * c]     = fmaxf(x, 0.f);
            h2_s[r * 65 + g * 16 + 2 * c + 1] = fmaxf(y, 0.f);
        }
    }
    __syncthreads();
    {   // pred = h2 @ W3 + b3 ; squared error partial
        int r = tid >> 2, g = tid & 3;
        float s = 0.f;
#pragma unroll
        for (int i = 0; i < 16; i++) s += h2_s[r * 65 + g * 16 + i] * W3[g * 16 + i];
        s += __shfl_xor_sync(0xffffffffu, s, 1);
        s += __shfl_xor_sync(0xffffffffu, s, 2);
        if (g == 0) {
            float p = s + b3[0];
            predOut[row0 + r] = p;
            float d = p - qy[row0 + r];
            red[r] = d * d;
        }
    }
    __syncthreads();
    if (tid < 32) {
        float v = red[tid] + red[tid + 32];
        v += __shfl_xor_sync(0xffffffffu, v, 16);
        v += __shfl_xor_sync(0xffffffffu, v, 8);
        v += __shfl_xor_sync(0xffffffffu, v, 4);
        v += __shfl_xor_sync(0xffffffffu, v, 2);
        v += __shfl_xor_sync(0xffffffffu, v, 1);
        if (tid == 0) g_loss_part[blockIdx.x] = v;
    }
}

// ---------------- deterministic loss finalize ----------------
__global__ void k_finalize(float* __restrict__ out) {
    __shared__ float s[1024];
    int t = threadIdx.x;
    s[t] = g_loss_part[t];
    __syncthreads();
    for (int st = 512; st > 0; st >>= 1) {
        if (t < st) s[t] += s[t + st];
        __syncthreads();
    }
    if (t == 0) out[0] = s[0] / (float)BQ;
}

// ---------------- launcher ----------------
extern "C" void kernel_launch(void* const* d_in, const int* in_sizes, int n_in,
                              void* d_out, int out_size) {
    const float* support_x  = (const float*)d_in[0];
    const float* support_y  = (const float*)d_in[1];
    const float* query_x    = (const float*)d_in[2];
    const float* query_y    = (const float*)d_in[3];
    const float* base_W     = (const float*)d_in[4];
    const float* base_b     = (const float*)d_in[5];
    const float* kp_W       = (const float*)d_in[6];
    const float* kp_b       = (const float*)d_in[7];
    const float* vp_W       = (const float*)d_in[8];
    const float* vp_b       = (const float*)d_in[9];
    const float* mem_keys   = (const float*)d_in[10];
    const float* mem_values = (const float*)d_in[11];
    const float* mem_age    = (const float*)d_in[12];
    const float* c1_W       = (const float*)d_in[13];
    const float* c1_b       = (const float*)d_in[14];
    const float* c2_W       = (const float*)d_in[15];
    const float* c2_b       = (const float*)d_in[16];
    const float* c3_W       = (const float*)d_in[17];
    const float* c3_b       = (const float*)d_in[18];
    float* out = (float*)d_out;

    float *p_sf, *p_pk, *p_pv, *p_pred_fb, *p_retr_fb;
    cudaGetSymbolAddress((void**)&p_sf, g_support_feat);
    cudaGetSymbolAddress((void**)&p_pk, g_proj_keys);
    cudaGetSymbolAddress((void**)&p_pv, g_proj_vals);
    cudaGetSymbolAddress((void**)&p_pred_fb, g_pred_fb);
    cudaGetSymbolAddress((void**)&p_retr_fb, g_retr_fb);

    // direct-into-output layout: [meta_loss(1) | query_pred(BQ) | retrieved(BQ*VAL)]
    float* predBuf = (out_size >= 1 + BQ)            ? out + 1      : p_pred_fb;
    float* retrBuf = (out_size >= 1 + BQ + BQ * VAL) ? out + 1 + BQ : p_retr_fb;

    const int qf_smem  = QF_SMEM_FLOATS * 4;
    const int at_smem  = AT_SMEM_FLOATS * 4;
    const int mlp_smem = MLP_SMEM_FLOATS * 4;
    cudaFuncSetAttribute(k_qfeat, cudaFuncAttributeMaxDynamicSharedMemorySize, qf_smem);
    cudaFuncSetAttribute(k_attn,  cudaFuncAttributeMaxDynamicSharedMemorySize, at_smem);
    cudaFuncSetAttribute(k_mlp,   cudaFuncAttributeMaxDynamicSharedMemorySize, mlp_smem);

    // support pipeline (tiny)
    k_linear<<<BSS * KEY / 256, 256>>>(support_x, base_W, base_b, p_sf, DIN, KEY);
    k_linear<<<BSS * KEY / 256, 256>>>(p_sf, kp_W, kp_b, p_pk, KEY, KEY);
    k_linear<<<BSS * VAL / 256, 256>>>(support_y, vp_W, vp_b, p_pv, VAL, VAL);
    k_rank<<<8, 128>>>(mem_age);
    k_scatter<<<NSLOT, 192>>>(mem_keys, mem_values);

    // query pipeline (big)
    k_qfeat<<<BQ / 64, 256, qf_smem>>>(query_x, base_W, base_b, kp_W, kp_b);
    k_attn<<<BQ / 64, 256, at_smem>>>(retrBuf);
    k_mlp<<<BQ / 64, 256, mlp_smem>>>(query_y, retrBuf, predBuf,
                                      c1_W, c1_b, c2_W, c2_b, c3_W, c3_b);
    k_finalize<<<1, 1024>>>(out);
}

// round 6
// speedup vs baseline: 4.6403x; 1.0007x over previous
#include <cuda_runtime.h>

#define MEM   1000
#define NSLOT 1024          /* padded slot count (rows 1000..1023 zero) */
#define KEY   64
#define VAL   128
#define DIN   512
#define BSS   512
#define BQ    65536

typedef unsigned long long u64;

// ---------------- packed f32x2 helpers (Blackwell sm_103a) ----------------
#define PACKF_F32X2(out, a, b) \
    asm("mov.b64 %0, {%1, %2};" : "=l"(out) : "f"(a), "f"(b))
#define UNPACKF_F32X2(a, b, in) \
    asm("mov.b64 {%0, %1}, %2;" : "=f"(a), "=f"(b) : "l"(in))
#define FMA_F32X2(d, a, b, c) \
    asm("fma.rn.f32x2 %0, %1, %2, %3;" : "=l"(d) : "l"(a), "l"(b), "l"(c))
#define MUL_F32X2(out, a, b) \
    asm("mul.rn.f32x2 %0, %1, %2;" : "=l"(out) : "l"(a), "l"(b))

// ---------------- device scratch (no allocations allowed) ----------------
__device__ __align__(16) float g_support_feat[BSS * KEY];
__device__ __align__(16) float g_proj_keys[BSS * KEY];
__device__ __align__(16) float g_proj_vals[BSS * VAL];
__device__             int   g_rank[MEM];
__device__ __align__(16) float g_new_keys[NSLOT * KEY];
__device__ __align__(16) float g_new_values[NSLOT * VAL];
__device__ __align__(16) float g_query_feat[BQ * KEY];
__device__ __align__(16) float g_proj_q[BQ * KEY];
__device__ __align__(16) float g_retr_fb[BQ * VAL];   // fallback if out too small
__device__ __align__(16) float g_pred_fb[BQ];
__device__             float g_loss_part[BQ / 64];

// ---------------- tiny generic linear: Y[r,c] = X[r,:K] @ W[:K,c] + b[c] ----------------
__global__ void k_linear(const float* __restrict__ X, const float* __restrict__ W,
                         const float* __restrict__ b, float* __restrict__ Y,
                         int K, int N) {
    int idx = blockIdx.x * blockDim.x + threadIdx.x;
    int r = idx / N, c = idx % N;
    float acc = b[c];
    const float* xr = X + r * K;
    for (int k = 0; k < K; k++) acc += xr[k] * W[k * N + c];
    Y[idx] = acc;
}

// ---------------- rank of each memory slot (parallel over 8 blocks) ----------------
__global__ void k_rank(const float* __restrict__ age) {
    __shared__ float a[MEM];
    int t = threadIdx.x;           // 128
    for (int i = t; i < MEM; i += 128) a[i] = age[i];
    __syncthreads();
    int j = blockIdx.x * 128 + t;
    if (j < MEM) {
        float aj = a[j];
        int cnt = 0;
        for (int i = 0; i < MEM; i++) {
            float ai = a[i];
            cnt += (ai > aj) || (ai == aj && i < j);   // stable tie-break like top_k
        }
        g_rank[j] = cnt;
    }
}

// ---------------- build new_keys / new_values (evict top-BS oldest; zero pad tail) ----------------
__global__ void k_scatter(const float* __restrict__ mk, const float* __restrict__ mv) {
    int j = blockIdx.x;        // 0..NSLOT-1
    int t = threadIdx.x;       // 192 threads
    if (j >= MEM) {            // padded rows: zero (finite so GEMM stays NaN-free)
        if (t < KEY) g_new_keys[j * KEY + t] = 0.f;
        else         g_new_values[j * VAL + (t - KEY)] = 0.f;
        return;
    }
    int r = g_rank[j];
    if (t < KEY) {
        g_new_keys[j * KEY + t] = (r < BSS) ? g_proj_keys[r * KEY + t] : mk[j * KEY + t];
    } else {
        int c = t - KEY;
        g_new_values[j * VAL + c] = (r < BSS) ? g_proj_vals[r * VAL + c] : mv[j * VAL + c];
    }
}

// ---------------- fused: query_feat = qx@base_W+b ; proj_q = query_feat@kp_W+kp_b ----------------
// base_W streamed in 64-k chunks (smem 49KB -> 3-4 blocks/SM); inner loop f32x2.
#define QF_BC 0
#define QF_AS (64 * 64)
#define QF_KP (64 * 64 + 64 * 68)
#define QF_SMEM_FLOATS (64 * 64 + 64 * 68 + 64 * 64)
__global__ void k_qfeat(const float* __restrict__ qx, const float* __restrict__ bW,
                        const float* __restrict__ bb, const float* __restrict__ kpW,
                        const float* __restrict__ kpb) {
    extern __shared__ float sm[];
    float* Bc   = sm + QF_BC;     // [64k][64c] current chunk of base_W
    float* A_s  = sm + QF_AS;     // [64r][68]
    float* kp_s = sm + QF_KP;     // [64][64]
    int tid = threadIdx.x;
    int tx = tid & 15, ty = tid >> 4;
    int row0 = blockIdx.x * 64;

    for (int i = tid; i < KEY * KEY / 4; i += 256)
        ((float4*)kp_s)[i] = ((const float4*)kpW)[i];

    u64 acc[4][2];                 // [row i][col-pair p]
#pragma unroll
    for (int i = 0; i < 4; i++) { acc[i][0] = 0ULL; acc[i][1] = 0ULL; }

    for (int kc = 0; kc < DIN / 64; kc++) {
        __syncthreads();
        for (int i = tid; i < 1024; i += 256)          // Bc chunk: contiguous
            ((float4*)Bc)[i] = ((const float4*)(bW + kc * 4096))[i];
        for (int i = tid; i < 4096; i += 256) {
            int r = i >> 6, kk = i & 63;
            A_s[r * 68 + kk] = qx[(row0 + r) * DIN + kc * 64 + kk];
        }
        __syncthreads();
#pragma unroll 8
        for (int k = 0; k < 64; k++) {
            ulonglong2 b2 = *(const ulonglong2*)&Bc[k * 64 + tx * 4];
#pragma unroll
            for (int i = 0; i < 4; i++) {
                float a = A_s[(ty * 4 + i) * 68 + k];
                u64 a2; PACKF_F32X2(a2, a, a);
                FMA_F32X2(acc[i][0], a2, b2.x, acc[i][0]);
                FMA_F32X2(acc[i][1], a2, b2.y, acc[i][1]);
            }
        }
    }
    __syncthreads();  // done reading A_s; reuse it as feat_s
    float* feat_s = A_s;
    float4 bias = *(const float4*)&bb[tx * 4];
#pragma unroll
    for (int i = 0; i < 4; i++) {
        int r = ty * 4 + i;
        float v0, v1, v2, v3;
        UNPACKF_F32X2(v0, v1, acc[i][0]);
        UNPACKF_F32X2(v2, v3, acc[i][1]);
        float4 v = make_float4(v0 + bias.x, v1 + bias.y, v2 + bias.z, v3 + bias.w);
        *(float4*)&feat_s[r * 68 + tx * 4] = v;
        *(float4*)&g_query_feat[(row0 + r) * KEY + tx * 4] = v;
    }
    __syncthreads();

    // proj_q = feat @ kp_W + kp_b  (64-k, f32x2)
    u64 acc2[4][2];
#pragma unroll
    for (int i = 0; i < 4; i++) { acc2[i][0] = 0ULL; acc2[i][1] = 0ULL; }
#pragma unroll 8
    for (int k = 0; k < KEY; k++) {
        ulonglong2 b2 = *(const ulonglong2*)&kp_s[k * KEY + tx * 4];
#pragma unroll
        for (int i = 0; i < 4; i++) {
            float a = feat_s[(ty * 4 + i) * 68 + k];
            u64 a2; PACKF_F32X2(a2, a, a);
            FMA_F32X2(acc2[i][0], a2, b2.x, acc2[i][0]);
            FMA_F32X2(acc2[i][1], a2, b2.y, acc2[i][1]);
        }
    }
    float4 kb = *(const float4*)&kpb[tx * 4];
#pragma unroll
    for (int i = 0; i < 4; i++) {
        int r = ty * 4 + i;
        float v0, v1, v2, v3;
        UNPACKF_F32X2(v0, v1, acc2[i][0]);
        UNPACKF_F32X2(v2, v3, acc2[i][1]);
        float4 v = make_float4(v0 + kb.x, v1 + kb.y, v2 + kb.z, v3 + kb.w);
        *(float4*)&g_proj_q[(row0 + r) * KEY + tx * 4] = v;
    }
}

// ---------------- flash attention: 128-row tiles, crossbar-optimized ----------------
// Block = 128 query rows, 256 threads, CHUNK=64 slots, 16 chunks.
// GEMM1: thread = 4 slots x 8 rows; b-operand = 2x LDS128 of qT (conflict-free).
// ws layout [slot][row] (stride 132): GEMM1 stores via STS.128, GEMM2 a-reads broadcast.
// GEMM2: thread = 8 rows x 8 cols; b-operand 2x LDS128 amortized over 8 rows.
#define AT_CHUNK 64
#define AT_QT 0
#define AT_KS (64 * 132)
#define AT_VS (AT_KS + 64 * 68)
#define AT_WS (AT_VS + 64 * 128)
#define AT_SC (AT_WS + 64 * 132)
#define AT_LI (AT_SC + 128)
#define AT_SMEM_FLOATS (AT_LI + 128)
__global__ void __launch_bounds__(256) k_attn(float* __restrict__ outR) {
    extern __shared__ float sm[];
    float* qT = sm + AT_QT;     // [64 k][132] : qT[k*132 + r], r 0..127
    float* ks = sm + AT_KS;     // [64 j][68]  : ks[j*68 + k]
    float* vs = sm + AT_VS;     // [64 j][128] : vs[j*128 + c]
    float* ws = sm + AT_WS;     // [64 j][132] : ws[j*132 + r]  (scores then weights)
    float* sc = sm + AT_SC;     // [128] per-row rescale
    float* li = sm + AT_LI;     // [128] per-row 1/l
    int tid = threadIdx.x;
    int tx = tid & 15, ty = tid >> 4;
    int r_e = tid >> 1, h = tid & 1;       // exp phase: 2 threads per row
    int row0 = blockIdx.x * 128;

    // load Q tile transposed (once). coalesced gmem reads.
    for (int idx = tid; idx < 128 * 64; idx += 256) {
        int r = idx >> 6, k = idx & 63;
        qT[k * 132 + r] = g_proj_q[(row0 + r) * KEY + k];
    }

    u64 acc[8][4];          // [row i][col-pair p] rows ty*8+i, cols tx*4(+64)
#pragma unroll
    for (int i = 0; i < 8; i++)
#pragma unroll
        for (int p = 0; p < 4; p++) acc[i][p] = 0ULL;
    float m = -1e30f, l = 0.f;

    for (int ch = 0; ch < NSLOT / AT_CHUNK; ch++) {
        int m0 = ch * AT_CHUNK;
        __syncthreads();   // prev GEMM2 done with vs/ws (covers qT stores on iter 0)
        for (int q = tid; q < 1024; q += 256) {            // ks: 64x64 as float4
            int j = q >> 4, c4 = q & 15;
            *(float4*)&ks[j * 68 + c4 * 4] =
                *(const float4*)&g_new_keys[(m0 + j) * KEY + c4 * 4];
        }
        for (int q = tid; q < 2048; q += 256)              // vs: straight copy
            ((float4*)vs)[q] = ((const float4*)(g_new_values + m0 * VAL))[q];
        __syncthreads();

        // ---- GEMM1: s[slot j=ty*4+jj][rows tx*4..+3 and 64+tx*4..+3] ----
        {
            u64 s4[4][4];
#pragma unroll
            for (int jj = 0; jj < 4; jj++)
#pragma unroll
                for (int p = 0; p < 4; p++) s4[jj][p] = 0ULL;
#pragma unroll 8
            for (int k = 0; k < 64; k++) {
                ulonglong2 bq1 = *(const ulonglong2*)&qT[k * 132 + tx * 4];
                ulonglong2 bq2 = *(const ulonglong2*)&qT[k * 132 + 64 + tx * 4];
#pragma unroll
                for (int jj = 0; jj < 4; jj++) {
                    float a = ks[(ty * 4 + jj) * 68 + k];
                    u64 a2; PACKF_F32X2(a2, a, a);
                    FMA_F32X2(s4[jj][0], a2, bq1.x, s4[jj][0]);
                    FMA_F32X2(s4[jj][1], a2, bq1.y, s4[jj][1]);
                    FMA_F32X2(s4[jj][2], a2, bq2.x, s4[jj][2]);
                    FMA_F32X2(s4[jj][3], a2, bq2.y, s4[jj][3]);
                }
            }
#pragma unroll
            for (int jj = 0; jj < 4; jj++) {
                int j = ty * 4 + jj;
                *(ulonglong2*)&ws[j * 132 + tx * 4] =
                    make_ulonglong2(s4[jj][0], s4[jj][1]);
                *(ulonglong2*)&ws[j * 132 + 64 + tx * 4] =
                    make_ulonglong2(s4[jj][2], s4[jj][3]);
            }
        }
        __syncthreads();

        // ---- exp phase: row r_e, slots h*32..h*32+31 (branchless online max) ----
        {
            int base = h * 32;
            int lim = MEM - m0 - base;      // jj < lim is a real slot
            float raw[32];
            float mx = -1e30f;
#pragma unroll
            for (int jj = 0; jj < 32; jj++) {
                float s = ws[(base + jj) * 132 + r_e];
                raw[jj] = s;
                if (jj < lim && s > mx) mx = s;
            }
            mx = fmaxf(mx, __shfl_xor_sync(0xffffffffu, mx, 1));
            float mnew = fmaxf(m, mx);
            float scl = __expf(m - mnew);
            float ls = 0.f;
#pragma unroll
            for (int jj = 0; jj < 32; jj++) {
                float w = (jj < lim) ? __expf(raw[jj] - mnew) : 0.f;
                ws[(base + jj) * 132 + r_e] = w;
                ls += w;
            }
            ls += __shfl_xor_sync(0xffffffffu, ls, 1);
            l = l * scl + ls;
            m = mnew;
            if (h == 0) sc[r_e] = scl;
        }
        __syncthreads();

        // ---- GEMM2: acc[rows ty*8+i][cols tx*4..+3, 64+tx*4..+3] ----
#pragma unroll
        for (int i = 0; i < 8; i++) {
            float s = sc[ty * 8 + i];
            u64 s2; PACKF_F32X2(s2, s, s);
#pragma unroll
            for (int p = 0; p < 4; p++) MUL_F32X2(acc[i][p], acc[i][p], s2);
        }
#pragma unroll 4
        for (int j = 0; j < 64; j++) {
            ulonglong2 bA = *(const ulonglong2*)&vs[j * 128 + tx * 4];
            ulonglong2 bB = *(const ulonglong2*)&vs[j * 128 + 64 + tx * 4];
#pragma unroll
            for (int i = 0; i < 8; i++) {
                float a = ws[j * 132 + ty * 8 + i];
                u64 a2; PACKF_F32X2(a2, a, a);
                FMA_F32X2(acc[i][0], a2, bA.x, acc[i][0]);
                FMA_F32X2(acc[i][1], a2, bA.y, acc[i][1]);
                FMA_F32X2(acc[i][2], a2, bB.x, acc[i][2]);
                FMA_F32X2(acc[i][3], a2, bB.y, acc[i][3]);
            }
        }
    }

    if (h == 0) li[r_e] = 1.0f / l;
    __syncthreads();

    // epilogue: unpack, normalize, scalar stores (out is only 4B-aligned)
#pragma unroll
    for (int i = 0; i < 8; i++) {
        int r = ty * 8 + i;
        float linv = li[r];
        float* op = outR + (size_t)(row0 + r) * VAL;
#pragma unroll
        for (int p = 0; p < 4; p++) {
            float lo, hi;
            UNPACKF_F32X2(lo, hi, acc[i][p]);
            int c = (p < 2) ? (tx * 4 + p * 2) : (64 + tx * 4 + (p - 2) * 2);
            op[c]     = lo * linv;
            op[c + 1] = hi * linv;
        }
    }
}

// ---------------- fused controller MLP + per-block loss partial (f32x2) ----------------
#define MLP_W1   24576          /* 192*128 */
#define MLP_AUG  (64 * 193)
#define MLP_H1   (64 * 129)
#define MLP_H2   (64 * 65)
#define MLP_SMEM_FLOATS (MLP_W1 + MLP_AUG + MLP_H1 + MLP_H2 + 64)
__global__ void k_mlp(const float* __restrict__ qy, const float* retrIn, float* predOut,
                      const float* __restrict__ W1, const float* __restrict__ b1,
                      const float* __restrict__ W2, const float* __restrict__ b2,
                      const float* __restrict__ W3, const float* __restrict__ b3) {
    extern __shared__ float sm[];
    float* W1_s  = sm;
    float* aug_s = sm + MLP_W1;
    float* h1_s  = aug_s + MLP_AUG;
    float* h2_s  = h1_s + MLP_H1;
    float* red   = h2_s + MLP_H2;
    int tid = threadIdx.x;
    int row0 = blockIdx.x * 64;

    for (int i = tid; i < MLP_W1 / 4; i += 256)
        ((float4*)W1_s)[i] = ((const float4*)W1)[i];
    for (int i = tid; i < 64 * 192; i += 256) {
        int r = i / 192, c = i % 192;
        float v = (c < KEY) ? g_query_feat[(row0 + r) * KEY + c]
                            : retrIn[(size_t)(row0 + r) * VAL + (c - KEY)];
        aug_s[r * 193 + c] = v;
    }
    __syncthreads();

    {   // h1 = relu(aug @ W1 + b1)   [64 x 128], f32x2: 16 col-pairs/thread
        int r = tid & 63, g = tid >> 6;
        u64 acc[16];
#pragma unroll
        for (int c = 0; c < 16; c++) {
            float x = b1[g * 32 + 2 * c], y = b1[g * 32 + 2 * c + 1];
            PACKF_F32X2(acc[c], x, y);
        }
        for (int k = 0; k < 192; k++) {
            float a = aug_s[r * 193 + k];
            u64 a2; PACKF_F32X2(a2, a, a);
            const ulonglong2* wr = (const ulonglong2*)(W1_s + k * 128 + g * 32);
#pragma unroll
            for (int q = 0; q < 8; q++) {
                ulonglong2 w = wr[q];
                FMA_F32X2(acc[2 * q],     a2, w.x, acc[2 * q]);
                FMA_F32X2(acc[2 * q + 1], a2, w.y, acc[2 * q + 1]);
            }
        }
#pragma unroll
        for (int c = 0; c < 16; c++) {
            float x, y;
            UNPACKF_F32X2(x, y, acc[c]);
            h1_s[r * 129 + g * 32 + 2 * c]     = fmaxf(x, 0.f);
            h1_s[r * 129 + g * 32 + 2 * c + 1] = fmaxf(y, 0.f);
        }
    }
    __syncthreads();
    float* W2_s = aug_s;
    for (int i = tid; i < 128 * 64 / 4; i += 256)
        ((float4*)W2_s)[i] = ((const float4*)W2)[i];
    __syncthreads();

    {   // h2 = relu(h1 @ W2 + b2)   [64 x 64], f32x2: 8 col-pairs/thread
        int r = tid & 63, g = tid >> 6;
        u64 acc[8];
#pragma unroll
        for (int c = 0; c < 8; c++) {
            float x = b2[g * 16 + 2 * c], y = b2[g * 16 + 2 * c + 1];
            PACKF_F32X2(acc[c], x, y);
        }
        for (int k = 0; k < 128; k++) {
            float a = h1_s[r * 129 + k];
            u64 a2; PACKF_F32X2(a2, a, a);
            const ulonglong2* wr = (const ulonglong2*)(W2_s + k * 64 + g * 16);
#pragma unroll
            for (int q = 0; q < 4; q++) {
                ulonglong2 w = wr[q];
                FMA_F32X2(acc[2 * q],     a2, w.x, acc[2 * q]);
                FMA_F32X2(acc[2 * q + 1], a2, w.y, acc[2 * q + 1]);
            }
        }
#pragma unroll
        for (int c = 0; c < 8; c++) {
            float x, y;
            UNPACKF_F32X2(x, y, acc[c]);
            h2_s[r * 65 + g * 16 + 2 * c]     = fmaxf(x, 0.f);
            h2_s[r * 65 + g * 16 + 2 * c + 1] = fmaxf(y, 0.f);
        }
    }
    __syncthreads();
    {   // pred = h2 @ W3 + b3 ; squared error partial
        int r = tid >> 2, g = tid & 3;
        float s = 0.f;
#pragma unroll
        for (int i = 0; i < 16; i++) s += h2_s[r * 65 + g * 16 + i] * W3[g * 16 + i];
        s += __shfl_xor_sync(0xffffffffu, s, 1);
        s += __shfl_xor_sync(0xffffffffu, s, 2);
        if (g == 0) {
            float p = s + b3[0];
            predOut[row0 + r] = p;
            float d = p - qy[row0 + r];
            red[r] = d * d;
        }
    }
    __syncthreads();
    if (tid < 32) {
        float v = red[tid] + red[tid + 32];
        v += __shfl_xor_sync(0xffffffffu, v, 16);
        v += __shfl_xor_sync(0xffffffffu, v, 8);
        v += __shfl_xor_sync(0xffffffffu, v, 4);
        v += __shfl_xor_sync(0xffffffffu, v, 2);
        v += __shfl_xor_sync(0xffffffffu, v, 1);
        if (tid == 0) g_loss_part[blockIdx.x] = v;
    }
}

// ---------------- deterministic loss finalize ----------------
__global__ void k_finalize(float* __restrict__ out) {
    __shared__ float s[1024];
    int t = threadIdx.x;
    s[t] = g_loss_part[t];
    __syncthreads();
    for (int st = 512; st > 0; st >>= 1) {
        if (t < st) s[t] += s[t + st];
        __syncthreads();
    }
    if (t == 0) out[0] = s[0] / (float)BQ;
}

// ---------------- launcher ----------------
extern "C" void kernel_launch(void* const* d_in, const int* in_sizes, int n_in,
                              void* d_out, int out_size) {
    const float* support_x  = (const float*)d_in[0];
    const float* support_y  = (const float*)d_in[1];
    const float* query_x    = (const float*)d_in[2];
    const float* query_y    = (const float*)d_in[3];
    const float* base_W     = (const float*)d_in[4];
    const float* base_b     = (const float*)d_in[5];
    const float* kp_W       = (const float*)d_in[6];
    const float* kp_b       = (const float*)d_in[7];
    const float* vp_W       = (const float*)d_in[8];
    const float* vp_b       = (const float*)d_in[9];
    const float* mem_keys   = (const float*)d_in[10];
    const float* mem_values = (const float*)d_in[11];
    const float* mem_age    = (const float*)d_in[12];
    const float* c1_W       = (const float*)d_in[13];
    const float* c1_b       = (const float*)d_in[14];
    const float* c2_W       = (const float*)d_in[15];
    const float* c2_b       = (const float*)d_in[16];
    const float* c3_W       = (const float*)d_in[17];
    const float* c3_b       = (const float*)d_in[18];
    float* out = (float*)d_out;

    float *p_sf, *p_pk, *p_pv, *p_pred_fb, *p_retr_fb;
    cudaGetSymbolAddress((void**)&p_sf, g_support_feat);
    cudaGetSymbolAddress((void**)&p_pk, g_proj_keys);
    cudaGetSymbolAddress((void**)&p_pv, g_proj_vals);
    cudaGetSymbolAddress((void**)&p_pred_fb, g_pred_fb);
    cudaGetSymbolAddress((void**)&p_retr_fb, g_retr_fb);

    // direct-into-output layout: [meta_loss(1) | query_pred(BQ) | retrieved(BQ*VAL)]
    float* predBuf = (out_size >= 1 + BQ)            ? out + 1      : p_pred_fb;
    float* retrBuf = (out_size >= 1 + BQ + BQ * VAL) ? out + 1 + BQ : p_retr_fb;

    const int qf_smem  = QF_SMEM_FLOATS * 4;
    const int at_smem  = AT_SMEM_FLOATS * 4;
    const int mlp_smem = MLP_SMEM_FLOATS * 4;
    cudaFuncSetAttribute(k_qfeat, cudaFuncAttributeMaxDynamicSharedMemorySize, qf_smem);
    cudaFuncSetAttribute(k_attn,  cudaFuncAttributeMaxDynamicSharedMemorySize, at_smem);
    cudaFuncSetAttribute(k_mlp,   cudaFuncAttributeMaxDynamicSharedMemorySize, mlp_smem);

    // support pipeline (tiny)
    k_linear<<<BSS * KEY / 256, 256>>>(support_x, base_W, base_b, p_sf, DIN, KEY);
    k_linear<<<BSS * KEY / 256, 256>>>(p_sf, kp_W, kp_b, p_pk, KEY, KEY);
    k_linear<<<BSS * VAL / 256, 256>>>(support_y, vp_W, vp_b, p_pv, VAL, VAL);
    k_rank<<<8, 128>>>(mem_age);
    k_scatter<<<NSLOT, 192>>>(mem_keys, mem_values);

    // query pipeline (big)
    k_qfeat<<<BQ / 64, 256, qf_smem>>>(query_x, base_W, base_b, kp_W, kp_b);
    k_attn<<<BQ / 128, 256, at_smem>>>(retrBuf);
    k_mlp<<<BQ / 64, 256, mlp_smem>>>(query_y, retrBuf, predBuf,
                                      c1_W, c1_b, c2_W, c2_b, c3_W, c3_b);
    k_finalize<<<1, 1024>>>(out);
}

// round 7
// speedup vs baseline: 4.7858x; 1.0314x over previous
#include <cuda_runtime.h>

#define MEM   1000
#define NSLOT 1024          /* padded slot count (rows 1000..1023 zero) */
#define KEY   64
#define VAL   128
#define DIN   512
#define BSS   512
#define BQ    65536

typedef unsigned long long u64;

// ---------------- packed f32x2 helpers (Blackwell sm_103a) ----------------
#define PACKF_F32X2(out, a, b) \
    asm("mov.b64 %0, {%1, %2};" : "=l"(out) : "f"(a), "f"(b))
#define UNPACKF_F32X2(a, b, in) \
    asm("mov.b64 {%0, %1}, %2;" : "=f"(a), "=f"(b) : "l"(in))
#define FMA_F32X2(d, a, b, c) \
    asm("fma.rn.f32x2 %0, %1, %2, %3;" : "=l"(d) : "l"(a), "l"(b), "l"(c))
#define MUL_F32X2(out, a, b) \
    asm("mul.rn.f32x2 %0, %1, %2;" : "=l"(out) : "l"(a), "l"(b))

// ---------------- device scratch (no allocations allowed) ----------------
__device__ __align__(16) float g_bWkp[DIN * KEY];     // bW @ kpW fused weight
__device__ __align__(16) float g_bias2[KEY];          // bb @ kpW + kpb
__device__ __align__(16) float g_proj_keys[BSS * KEY];
__device__ __align__(16) float g_proj_vals[BSS * VAL];
__device__             int   g_rank[MEM];
__device__ __align__(16) float g_new_keys[NSLOT * KEY];
__device__ __align__(16) float g_new_values[NSLOT * VAL];
__device__ __align__(16) float g_query_feat[BQ * KEY];
__device__ __align__(16) float g_proj_q[BQ * KEY];
__device__ __align__(16) float g_retr_fb[BQ * VAL];   // fallback if out too small
__device__ __align__(16) float g_pred_fb[BQ];
__device__             float g_loss_part[BQ / 64];

// ---------------- fused: query_feat = qx@base_W+b ; proj_q = query_feat@kp_W+kp_b ----------------
// base_W streamed in 64-k chunks; inner loop f32x2.
// Blocks 0..7 additionally emit g_bWkp = bW@kpW; block 0 emits g_bias2 (for k_prep).
#define QF_BC 0
#define QF_AS (64 * 64)
#define QF_KP (64 * 64 + 64 * 68)
#define QF_SMEM_FLOATS (64 * 64 + 64 * 68 + 64 * 64)
__global__ void k_qfeat(const float* __restrict__ qx, const float* __restrict__ bW,
                        const float* __restrict__ bb, const float* __restrict__ kpW,
                        const float* __restrict__ kpb) {
    extern __shared__ float sm[];
    float* Bc   = sm + QF_BC;     // [64k][64c] current chunk of base_W
    float* A_s  = sm + QF_AS;     // [64r][68]
    float* kp_s = sm + QF_KP;     // [64][64]
    int tid = threadIdx.x;
    int tx = tid & 15, ty = tid >> 4;
    int row0 = blockIdx.x * 64;

    for (int i = tid; i < KEY * KEY / 4; i += 256)
        ((float4*)kp_s)[i] = ((const float4*)kpW)[i];

    u64 acc[4][2];                 // [row i][col-pair p]
#pragma unroll
    for (int i = 0; i < 4; i++) { acc[i][0] = 0ULL; acc[i][1] = 0ULL; }

    for (int kc = 0; kc < DIN / 64; kc++) {
        __syncthreads();
        for (int i = tid; i < 1024; i += 256)          // Bc chunk: contiguous
            ((float4*)Bc)[i] = ((const float4*)(bW + kc * 4096))[i];
        for (int i = tid; i < 4096; i += 256) {
            int r = i >> 6, kk = i & 63;
            A_s[r * 68 + kk] = qx[(row0 + r) * DIN + kc * 64 + kk];
        }
        __syncthreads();
#pragma unroll 8
        for (int k = 0; k < 64; k++) {
            ulonglong2 b2 = *(const ulonglong2*)&Bc[k * 64 + tx * 4];
#pragma unroll
            for (int i = 0; i < 4; i++) {
                float a = A_s[(ty * 4 + i) * 68 + k];
                u64 a2; PACKF_F32X2(a2, a, a);
                FMA_F32X2(acc[i][0], a2, b2.x, acc[i][0]);
                FMA_F32X2(acc[i][1], a2, b2.y, acc[i][1]);
            }
        }
    }
    __syncthreads();  // done reading A_s; reuse it as feat_s
    float* feat_s = A_s;
    float4 bias = *(const float4*)&bb[tx * 4];
#pragma unroll
    for (int i = 0; i < 4; i++) {
        int r = ty * 4 + i;
        float v0, v1, v2, v3;
        UNPACKF_F32X2(v0, v1, acc[i][0]);
        UNPACKF_F32X2(v2, v3, acc[i][1]);
        float4 v = make_float4(v0 + bias.x, v1 + bias.y, v2 + bias.z, v3 + bias.w);
        *(float4*)&feat_s[r * 68 + tx * 4] = v;
        *(float4*)&g_query_feat[(row0 + r) * KEY + tx * 4] = v;
    }
    __syncthreads();

    // proj_q = feat @ kp_W + kp_b  (64-k, f32x2)
    u64 acc2[4][2];
#pragma unroll
    for (int i = 0; i < 4; i++) { acc2[i][0] = 0ULL; acc2[i][1] = 0ULL; }
#pragma unroll 8
    for (int k = 0; k < KEY; k++) {
        ulonglong2 b2 = *(const ulonglong2*)&kp_s[k * KEY + tx * 4];
#pragma unroll
        for (int i = 0; i < 4; i++) {
            float a = feat_s[(ty * 4 + i) * 68 + k];
            u64 a2; PACKF_F32X2(a2, a, a);
            FMA_F32X2(acc2[i][0], a2, b2.x, acc2[i][0]);
            FMA_F32X2(acc2[i][1], a2, b2.y, acc2[i][1]);
        }
    }
    float4 kb = *(const float4*)&kpb[tx * 4];
#pragma unroll
    for (int i = 0; i < 4; i++) {
        int r = ty * 4 + i;
        float v0, v1, v2, v3;
        UNPACKF_F32X2(v0, v1, acc2[i][0]);
        UNPACKF_F32X2(v2, v3, acc2[i][1]);
        float4 v = make_float4(v0 + kb.x, v1 + kb.y, v2 + kb.z, v3 + kb.w);
        *(float4*)&g_proj_q[(row0 + r) * KEY + tx * 4] = v;
    }

    // byproduct: fused support weights (kp_s still resident in smem)
    if (blockIdx.x < 8) {
        int d0 = blockIdx.x * 64;
        for (int o = tid; o < 64 * 64; o += 256) {
            int dr = o >> 6, c = o & 63;
            const float* brow = bW + (size_t)(d0 + dr) * KEY;
            float a = 0.f;
            for (int k = 0; k < KEY; k++) a += brow[k] * kp_s[k * 64 + c];
            g_bWkp[(d0 + dr) * KEY + c] = a;
        }
    }
    if (blockIdx.x == 0 && tid < KEY) {
        float a = kpb[tid];
        for (int k = 0; k < KEY; k++) a += bb[k] * kp_s[k * 64 + tid];
        g_bias2[tid] = a;
    }
}

// ---------------- prep: proj_keys (fused weights), proj_vals, ranks — one kernel ----------------
__global__ void k_prep(const float* __restrict__ sx, const float* __restrict__ sy,
                       const float* __restrict__ vpW, const float* __restrict__ vpb,
                       const float* __restrict__ age) {
    __shared__ float a_s[MEM];
    int b = blockIdx.x, tid = threadIdx.x;
    if (b < 128) {                 // proj_keys = sx @ bWkp + bias2   [512 x 64]
        int idx = b * 256 + tid;
        int r = idx >> 6, c = idx & 63;
        float acc = g_bias2[c];
        const float* xr = sx + (size_t)r * DIN;
        for (int k = 0; k < DIN; k++) acc += xr[k] * g_bWkp[k * KEY + c];
        g_proj_keys[idx] = acc;
    } else if (b < 384) {          // proj_vals = sy @ vpW + vpb      [512 x 128]
        int idx = (b - 128) * 256 + tid;
        int r = idx >> 7, c = idx & 127;
        float acc = vpb[c];
        const float* yr = sy + (size_t)r * VAL;
        for (int k = 0; k < VAL; k++) acc += yr[k] * vpW[k * VAL + c];
        g_proj_vals[idx] = acc;
    } else {                       // rank: stable descending-age rank
        for (int i = tid; i < MEM; i += 256) a_s[i] = age[i];
        __syncthreads();
        int j = (b - 384) * 256 + tid;
        if (j < MEM) {
            float aj = a_s[j];
            int cnt = 0;
            for (int i = 0; i < MEM; i++) {
                float ai = a_s[i];
                cnt += (ai > aj) || (ai == aj && i < j);
            }
            g_rank[j] = cnt;
        }
    }
}

// ---------------- build new_keys / new_values (evict top-BS oldest; zero pad tail) ----------------
__global__ void k_scatter(const float* __restrict__ mk, const float* __restrict__ mv) {
    int j = blockIdx.x;        // 0..NSLOT-1
    int t = threadIdx.x;       // 192 threads
    if (j >= MEM) {            // padded rows: zero (finite so GEMM stays NaN-free)
        if (t < KEY) g_new_keys[j * KEY + t] = 0.f;
        else         g_new_values[j * VAL + (t - KEY)] = 0.f;
        return;
    }
    int r = g_rank[j];
    if (t < KEY) {
        g_new_keys[j * KEY + t] = (r < BSS) ? g_proj_keys[r * KEY + t] : mk[j * KEY + t];
    } else {
        int c = t - KEY;
        g_new_values[j * VAL + c] = (r < BSS) ? g_proj_vals[r * VAL + c] : mv[j * VAL + c];
    }
}

// ---------------- flash attention: 128-row tiles, crossbar-optimized ----------------
#define AT_CHUNK 64
#define AT_QT 0
#define AT_KS (64 * 132)
#define AT_VS (AT_KS + 64 * 68)
#define AT_WS (AT_VS + 64 * 128)
#define AT_SC (AT_WS + 64 * 132)
#define AT_LI (AT_SC + 128)
#define AT_SMEM_FLOATS (AT_LI + 128)
__global__ void __launch_bounds__(256) k_attn(float* __restrict__ outR) {
    extern __shared__ float sm[];
    float* qT = sm + AT_QT;     // [64 k][132] : qT[k*132 + r], r 0..127
    float* ks = sm + AT_KS;     // [64 j][68]  : ks[j*68 + k]
    float* vs = sm + AT_VS;     // [64 j][128] : vs[j*128 + c]
    float* ws = sm + AT_WS;     // [64 j][132] : ws[j*132 + r]  (scores then weights)
    float* sc = sm + AT_SC;     // [128] per-row rescale
    float* li = sm + AT_LI;     // [128] per-row 1/l
    int tid = threadIdx.x;
    int tx = tid & 15, ty = tid >> 4;
    int r_e = tid >> 1, h = tid & 1;       // exp phase: 2 threads per row
    int row0 = blockIdx.x * 128;

    // load Q tile transposed (once). coalesced gmem reads.
    for (int idx = tid; idx < 128 * 64; idx += 256) {
        int r = idx >> 6, k = idx & 63;
        qT[k * 132 + r] = g_proj_q[(row0 + r) * KEY + k];
    }

    u64 acc[8][4];          // [row i][col-pair p] rows ty*8+i, cols tx*4(+64)
#pragma unroll
    for (int i = 0; i < 8; i++)
#pragma unroll
        for (int p = 0; p < 4; p++) acc[i][p] = 0ULL;
    float m = -1e30f, l = 0.f;

    for (int ch = 0; ch < NSLOT / AT_CHUNK; ch++) {
        int m0 = ch * AT_CHUNK;
        __syncthreads();   // prev GEMM2 done with vs/ws (covers qT stores on iter 0)
        for (int q = tid; q < 1024; q += 256) {            // ks: 64x64 as float4
            int j = q >> 4, c4 = q & 15;
            *(float4*)&ks[j * 68 + c4 * 4] =
                *(const float4*)&g_new_keys[(m0 + j) * KEY + c4 * 4];
        }
        for (int q = tid; q < 2048; q += 256)              // vs: straight copy
            ((float4*)vs)[q] = ((const float4*)(g_new_values + m0 * VAL))[q];
        __syncthreads();

        // ---- GEMM1: s[slot j=ty*4+jj][rows tx*4..+3 and 64+tx*4..+3] ----
        {
            u64 s4[4][4];
#pragma unroll
            for (int jj = 0; jj < 4; jj++)
#pragma unroll
                for (int p = 0; p < 4; p++) s4[jj][p] = 0ULL;
#pragma unroll 8
            for (int k = 0; k < 64; k++) {
                ulonglong2 bq1 = *(const ulonglong2*)&qT[k * 132 + tx * 4];
                ulonglong2 bq2 = *(const ulonglong2*)&qT[k * 132 + 64 + tx * 4];
#pragma unroll
                for (int jj = 0; jj < 4; jj++) {
                    float a = ks[(ty * 4 + jj) * 68 + k];
                    u64 a2; PACKF_F32X2(a2, a, a);
                    FMA_F32X2(s4[jj][0], a2, bq1.x, s4[jj][0]);
                    FMA_F32X2(s4[jj][1], a2, bq1.y, s4[jj][1]);
                    FMA_F32X2(s4[jj][2], a2, bq2.x, s4[jj][2]);
                    FMA_F32X2(s4[jj][3], a2, bq2.y, s4[jj][3]);
                }
            }
#pragma unroll
            for (int jj = 0; jj < 4; jj++) {
                int j = ty * 4 + jj;
                *(ulonglong2*)&ws[j * 132 + tx * 4] =
                    make_ulonglong2(s4[jj][0], s4[jj][1]);
                *(ulonglong2*)&ws[j * 132 + 64 + tx * 4] =
                    make_ulonglong2(s4[jj][2], s4[jj][3]);
            }
        }
        __syncthreads();

        // ---- exp phase: row r_e, slots h*32..h*32+31 (branchless online max) ----
        {
            int base = h * 32;
            int lim = MEM - m0 - base;      // jj < lim is a real slot
            float raw[32];
            float mx = -1e30f;
#pragma unroll
            for (int jj = 0; jj < 32; jj++) {
                float s = ws[(base + jj) * 132 + r_e];
                raw[jj] = s;
                if (jj < lim && s > mx) mx = s;
            }
            mx = fmaxf(mx, __shfl_xor_sync(0xffffffffu, mx, 1));
            float mnew = fmaxf(m, mx);
            float scl = __expf(m - mnew);
            float ls = 0.f;
#pragma unroll
            for (int jj = 0; jj < 32; jj++) {
                float w = (jj < lim) ? __expf(raw[jj] - mnew) : 0.f;
                ws[(base + jj) * 132 + r_e] = w;
                ls += w;
            }
            ls += __shfl_xor_sync(0xffffffffu, ls, 1);
            l = l * scl + ls;
            m = mnew;
            if (h == 0) sc[r_e] = scl;
        }
        __syncthreads();

        // ---- GEMM2: acc[rows ty*8+i][cols tx*4..+3, 64+tx*4..+3] ----
#pragma unroll
        for (int i = 0; i < 8; i++) {
            float s = sc[ty * 8 + i];
            u64 s2; PACKF_F32X2(s2, s, s);
#pragma unroll
            for (int p = 0; p < 4; p++) MUL_F32X2(acc[i][p], acc[i][p], s2);
        }
#pragma unroll 4
        for (int j = 0; j < 64; j++) {
            ulonglong2 bA = *(const ulonglong2*)&vs[j * 128 + tx * 4];
            ulonglong2 bB = *(const ulonglong2*)&vs[j * 128 + 64 + tx * 4];
            float av[8];                       // 8 consecutive row-weights: 2x LDS128
            *(float4*)&av[0] = *(const float4*)&ws[j * 132 + ty * 8];
            *(float4*)&av[4] = *(const float4*)&ws[j * 132 + ty * 8 + 4];
#pragma unroll
            for (int i = 0; i < 8; i++) {
                u64 a2; PACKF_F32X2(a2, av[i], av[i]);
                FMA_F32X2(acc[i][0], a2, bA.x, acc[i][0]);
                FMA_F32X2(acc[i][1], a2, bA.y, acc[i][1]);
                FMA_F32X2(acc[i][2], a2, bB.x, acc[i][2]);
                FMA_F32X2(acc[i][3], a2, bB.y, acc[i][3]);
            }
        }
    }

    if (h == 0) li[r_e] = 1.0f / l;
    __syncthreads();

    // epilogue: unpack, normalize, scalar stores (out is only 4B-aligned)
#pragma unroll
    for (int i = 0; i < 8; i++) {
        int r = ty * 8 + i;
        float linv = li[r];
        float* op = outR + (size_t)(row0 + r) * VAL;
#pragma unroll
        for (int p = 0; p < 4; p++) {
            float lo, hi;
            UNPACKF_F32X2(lo, hi, acc[i][p]);
            int c = (p < 2) ? (tx * 4 + p * 2) : (64 + tx * 4 + (p - 2) * 2);
            op[c]     = lo * linv;
            op[c + 1] = hi * linv;
        }
    }
}

// ---------------- fused controller MLP + per-block loss partial (f32x2) ----------------
#define MLP_W1   24576          /* 192*128 */
#define MLP_AUG  (64 * 193)
#define MLP_H1   (64 * 129)
#define MLP_H2   (64 * 65)
#define MLP_SMEM_FLOATS (MLP_W1 + MLP_AUG + MLP_H1 + MLP_H2 + 64)
__global__ void k_mlp(const float* __restrict__ qy, const float* retrIn, float* predOut,
                      const float* __restrict__ W1, const float* __restrict__ b1,
                      const float* __restrict__ W2, const float* __restrict__ b2,
                      const float* __restrict__ W3, const float* __restrict__ b3) {
    extern __shared__ float sm[];
    float* W1_s  = sm;
    float* aug_s = sm + MLP_W1;
    float* h1_s  = aug_s + MLP_AUG;
    float* h2_s  = h1_s + MLP_H1;
    float* red   = h2_s + MLP_H2;
    int tid = threadIdx.x;
    int row0 = blockIdx.x * 64;

    for (int i = tid; i < MLP_W1 / 4; i += 256)
        ((float4*)W1_s)[i] = ((const float4*)W1)[i];
    for (int i = tid; i < 64 * 192; i += 256) {
        int r = i / 192, c = i % 192;
        float v = (c < KEY) ? g_query_feat[(row0 + r) * KEY + c]
                            : retrIn[(size_t)(row0 + r) * VAL + (c - KEY)];
        aug_s[r * 193 + c] = v;
    }
    __syncthreads();

    {   // h1 = relu(aug @ W1 + b1)   [64 x 128], f32x2: 16 col-pairs/thread
        int r = tid & 63, g = tid >> 6;
        u64 acc[16];
#pragma unroll
        for (int c = 0; c < 16; c++) {
            float x = b1[g * 32 + 2 * c], y = b1[g * 32 + 2 * c + 1];
            PACKF_F32X2(acc[c], x, y);
        }
        for (int k = 0; k < 192; k++) {
            float a = aug_s[r * 193 + k];
            u64 a2; PACKF_F32X2(a2, a, a);
            const ulonglong2* wr = (const ulonglong2*)(W1_s + k * 128 + g * 32);
#pragma unroll
            for (int q = 0; q < 8; q++) {
                ulonglong2 w = wr[q];
                FMA_F32X2(acc[2 * q],     a2, w.x, acc[2 * q]);
                FMA_F32X2(acc[2 * q + 1], a2, w.y, acc[2 * q + 1]);
            }
        }
#pragma unroll
        for (int c = 0; c < 16; c++) {
            float x, y;
            UNPACKF_F32X2(x, y, acc[c]);
            h1_s[r * 129 + g * 32 + 2 * c]     = fmaxf(x, 0.f);
            h1_s[r * 129 + g * 32 + 2 * c + 1] = fmaxf(y, 0.f);
        }
    }
    __syncthreads();
    float* W2_s = aug_s;
    for (int i = tid; i < 128 * 64 / 4; i += 256)
        ((float4*)W2_s)[i] = ((const float4*)W2)[i];
    __syncthreads();

    {   // h2 = relu(h1 @ W2 + b2)   [64 x 64], f32x2: 8 col-pairs/thread
        int r = tid & 63, g = tid >> 6;
        u64 acc[8];
#pragma unroll
        for (int c = 0; c < 8; c++) {
            float x = b2[g * 16 + 2 * c], y = b2[g * 16 + 2 * c + 1];
            PACKF_F32X2(acc[c], x, y);
        }
        for (int k = 0; k < 128; k++) {
            float a = h1_s[r * 129 + k];
            u64 a2; PACKF_F32X2(a2, a, a);
            const ulonglong2* wr = (const ulonglong2*)(W2_s + k * 64 + g * 16);
#pragma unroll
            for (int q = 0; q < 4; q++) {
                ulonglong2 w = wr[q];
                FMA_F32X2(acc[2 * q],     a2, w.x, acc[2 * q]);
                FMA_F32X2(acc[2 * q + 1], a2, w.y, acc[2 * q + 1]);
            }
        }
#pragma unroll
        for (int c = 0; c < 8; c++) {
            float x, y;
            UNPACKF_F32X2(x, y, acc[c]);
            h2_s[r * 65 + g * 16 + 2 * c]     = fmaxf(x, 0.f);
            h2_s[r * 65 + g * 16 + 2 * c + 1] = fmaxf(y, 0.f);
        }
    }
    __syncthreads();
    {   // pred = h2 @ W3 + b3 ; squared error partial
        int r = tid >> 2, g = tid & 3;
        float s = 0.f;
#pragma unroll
        for (int i = 0; i < 16; i++) s += h2_s[r * 65 + g * 16 + i] * W3[g * 16 + i];
        s += __shfl_xor_sync(0xffffffffu, s, 1);
        s += __shfl_xor_sync(0xffffffffu, s, 2);
        if (g == 0) {
            float p = s + b3[0];
            predOut[row0 + r] = p;
            float d = p - qy[row0 + r];
            red[r] = d * d;
        }
    }
    __syncthreads();
    if (tid < 32) {
        float v = red[tid] + red[tid + 32];
        v += __shfl_xor_sync(0xffffffffu, v, 16);
        v += __shfl_xor_sync(0xffffffffu, v, 8);
        v += __shfl_xor_sync(0xffffffffu, v, 4);
        v += __shfl_xor_sync(0xffffffffu, v, 2);
        v += __shfl_xor_sync(0xffffffffu, v, 1);
        if (tid == 0) g_loss_part[blockIdx.x] = v;
    }
}

// ---------------- deterministic loss finalize ----------------
__global__ void k_finalize(float* __restrict__ out) {
    __shared__ float s[1024];
    int t = threadIdx.x;
    s[t] = g_loss_part[t];
    __syncthreads();
    for (int st = 512; st > 0; st >>= 1) {
        if (t < st) s[t] += s[t + st];
        __syncthreads();
    }
    if (t == 0) out[0] = s[0] / (float)BQ;
}

// ---------------- launcher ----------------
extern "C" void kernel_launch(void* const* d_in, const int* in_sizes, int n_in,
                              void* d_out, int out_size) {
    const float* support_x  = (const float*)d_in[0];
    const float* support_y  = (const float*)d_in[1];
    const float* query_x    = (const float*)d_in[2];
    const float* query_y    = (const float*)d_in[3];
    const float* base_W     = (const float*)d_in[4];
    const float* base_b     = (const float*)d_in[5];
    const float* kp_W       = (const float*)d_in[6];
    const float* kp_b       = (const float*)d_in[7];
    const float* vp_W       = (const float*)d_in[8];
    const float* vp_b       = (const float*)d_in[9];
    const float* mem_keys   = (const float*)d_in[10];
    const float* mem_values = (const float*)d_in[11];
    const float* mem_age    = (const float*)d_in[12];
    const float* c1_W       = (const float*)d_in[13];
    const float* c1_b       = (const float*)d_in[14];
    const float* c2_W       = (const float*)d_in[15];
    const float* c2_b       = (const float*)d_in[16];
    const float* c3_W       = (const float*)d_in[17];
    const float* c3_b       = (const float*)d_in[18];
    float* out = (float*)d_out;

    float *p_pred_fb, *p_retr_fb;
    cudaGetSymbolAddress((void**)&p_pred_fb, g_pred_fb);
    cudaGetSymbolAddress((void**)&p_retr_fb, g_retr_fb);

    // direct-into-output layout: [meta_loss(1) | query_pred(BQ) | retrieved(BQ*VAL)]
    float* predBuf = (out_size >= 1 + BQ)            ? out + 1      : p_pred_fb;
    float* retrBuf = (out_size >= 1 + BQ + BQ * VAL) ? out + 1 + BQ : p_retr_fb;

    const int qf_smem  = QF_SMEM_FLOATS * 4;
    const int at_smem  = AT_SMEM_FLOATS * 4;
    const int mlp_smem = MLP_SMEM_FLOATS * 4;
    cudaFuncSetAttribute(k_qfeat, cudaFuncAttributeMaxDynamicSharedMemorySize, qf_smem);
    cudaFuncSetAttribute(k_attn,  cudaFuncAttributeMaxDynamicSharedMemorySize, at_smem);
    cudaFuncSetAttribute(k_mlp,   cudaFuncAttributeMaxDynamicSharedMemorySize, mlp_smem);

    // launch order arranged so k_attn is the 4th launch (ncu -s window)
    k_qfeat<<<BQ / 64, 256, qf_smem>>>(query_x, base_W, base_b, kp_W, kp_b);
    k_prep<<<388, 256>>>(support_x, support_y, vp_W, vp_b, mem_age);
    k_scatter<<<NSLOT, 192>>>(mem_keys, mem_values);
    k_attn<<<BQ / 128, 256, at_smem>>>(retrBuf);
    k_mlp<<<BQ / 64, 256, mlp_smem>>>(query_y, retrBuf, predBuf,
                                      c1_W, c1_b, c2_W, c2_b, c3_W, c3_b);
    k_finalize<<<1, 1024>>>(out);
}